// round 1
// baseline (speedup 1.0000x reference)
#include <cuda_runtime.h>
#include <math.h>

#define HIDDEN   2048
#define HEADS    16
#define HEAD_DIM 128
#define BATCH    2
#define SEQ      1024
#define MROWS    (BATCH*SEQ)

// ---------------- scratch (allocation-free: device globals) ----------------
__device__ float g_q[BATCH*HEADS*SEQ*HEAD_DIM];    // 16.8 MB each
__device__ float g_k[BATCH*HEADS*SEQ*HEAD_DIM];
__device__ float g_v[BATCH*HEADS*SEQ*HEAD_DIM];
__device__ float g_attn[MROWS*HIDDEN];

// ============================================================================
// K1/K4: fp32 SGEMM, C[2048x2048] = A[2048x2048] * W[2048x2048] (+bias)
// 128x128 block tile, BK=16, 256 threads, 8x8 per thread, reg-prefetch.
// transposed=1: write C in [B,HEADS,S,HEAD_DIM] layout (for QKV).
// ============================================================================
__global__ __launch_bounds__(256, 2) void sgemm2048_kernel(
    const float* __restrict__ A,
    const float* __restrict__ W0, const float* __restrict__ W1, const float* __restrict__ W2,
    float* __restrict__ D0, float* __restrict__ D1, float* __restrict__ D2,
    const float* __restrict__ bias, int transposed)
{
    const int z = blockIdx.z;
    const float* __restrict__ W = (z == 0) ? W0 : ((z == 1) ? W1 : W2);
    float* __restrict__ D       = (z == 0) ? D0 : ((z == 1) ? D1 : D2);

    __shared__ float As[16][132];   // transposed: As[k][m]
    __shared__ float Bs[16][132];   // Bs[k][n]

    const int t  = threadIdx.x;
    const int m0 = blockIdx.y * 128;
    const int n0 = blockIdx.x * 128;
    const int tm = (t >> 4) * 8;
    const int tn = (t & 15) * 8;

    // global-load mapping (each thread: 2 float4 of A, 2 float4 of B per k-tile)
    const int a_r = t >> 1;            // 0..127
    const int a_c = (t & 1) * 8;       // 0 or 8 (k offset within 16)
    const int b_r = t >> 4;            // 0..15  (k row)
    const int b_c = (t & 15) * 8;      // 0..120 (n offset)

    float acc[8][8];
#pragma unroll
    for (int i = 0; i < 8; ++i)
#pragma unroll
        for (int j = 0; j < 8; ++j) acc[i][j] = 0.f;

    float4 pa0, pa1, pb0, pb1;
    {
        const float* Ap = A + (size_t)(m0 + a_r) * HIDDEN + a_c;
        pa0 = *(const float4*)Ap;
        pa1 = *(const float4*)(Ap + 4);
        const float* Bp = W + (size_t)b_r * HIDDEN + n0 + b_c;
        pb0 = *(const float4*)Bp;
        pb1 = *(const float4*)(Bp + 4);
    }

    for (int kt = 0; kt < 128; ++kt) {
        // commit prefetched tile to smem
        As[a_c+0][a_r] = pa0.x; As[a_c+1][a_r] = pa0.y;
        As[a_c+2][a_r] = pa0.z; As[a_c+3][a_r] = pa0.w;
        As[a_c+4][a_r] = pa1.x; As[a_c+5][a_r] = pa1.y;
        As[a_c+6][a_r] = pa1.z; As[a_c+7][a_r] = pa1.w;
        *(float4*)&Bs[b_r][b_c]     = pb0;
        *(float4*)&Bs[b_r][b_c + 4] = pb1;
        __syncthreads();

        if (kt < 127) {
            const float* Ap = A + (size_t)(m0 + a_r) * HIDDEN + (kt + 1) * 16 + a_c;
            pa0 = *(const float4*)Ap;
            pa1 = *(const float4*)(Ap + 4);
            const float* Bp = W + (size_t)((kt + 1) * 16 + b_r) * HIDDEN + n0 + b_c;
            pb0 = *(const float4*)Bp;
            pb1 = *(const float4*)(Bp + 4);
        }

#pragma unroll
        for (int kk = 0; kk < 16; ++kk) {
            float4 a0 = *(const float4*)&As[kk][tm];
            float4 a1 = *(const float4*)&As[kk][tm + 4];
            float4 b0 = *(const float4*)&Bs[kk][tn];
            float4 b1 = *(const float4*)&Bs[kk][tn + 4];
            float av[8] = {a0.x, a0.y, a0.z, a0.w, a1.x, a1.y, a1.z, a1.w};
            float bv[8] = {b0.x, b0.y, b0.z, b0.w, b1.x, b1.y, b1.z, b1.w};
#pragma unroll
            for (int i = 0; i < 8; ++i)
#pragma unroll
                for (int j = 0; j < 8; ++j) acc[i][j] += av[i] * bv[j];
        }
        __syncthreads();
    }

    if (bias) {
        float bv[8];
#pragma unroll
        for (int j = 0; j < 8; ++j) bv[j] = bias[n0 + tn + j];
#pragma unroll
        for (int i = 0; i < 8; ++i)
#pragma unroll
            for (int j = 0; j < 8; ++j) acc[i][j] += bv[j];
    }

    if (transposed) {
        // n -> (h, d); m -> (b, s); write [B, HEADS, S, HEAD_DIM]
        const int h = (n0 + tn) >> 7;
        const int d = (n0 + tn) & 127;
#pragma unroll
        for (int i = 0; i < 8; ++i) {
            int m  = m0 + tm + i;
            int bb = m >> 10;
            int s  = m & 1023;
            float* dst = D + (((size_t)(bb * HEADS + h) * SEQ + s) << 7) + d;
            float4 w0 = {acc[i][0], acc[i][1], acc[i][2], acc[i][3]};
            float4 w1 = {acc[i][4], acc[i][5], acc[i][6], acc[i][7]};
            *(float4*)dst       = w0;
            *(float4*)(dst + 4) = w1;
        }
    } else {
#pragma unroll
        for (int i = 0; i < 8; ++i) {
            float* dst = D + (size_t)(m0 + tm + i) * HIDDEN + n0 + tn;
            float4 w0 = {acc[i][0], acc[i][1], acc[i][2], acc[i][3]};
            float4 w1 = {acc[i][4], acc[i][5], acc[i][6], acc[i][7]};
            *(float4*)dst       = w0;
            *(float4*)(dst + 4) = w1;
        }
    }
}

// ============================================================================
// K2: in-place RoPE on q and k, layout [B, HEADS, S, HEAD_DIM]
// ============================================================================
__global__ void rope_kernel(float* __restrict__ q, float* __restrict__ k)
{
    int idx = blockIdx.x * blockDim.x + threadIdx.x;
    if (idx >= BATCH * HEADS * SEQ * 64) return;
    int i  = idx & 63;
    int s  = (idx >> 6) & (SEQ - 1);
    int bh = idx >> 16;

    // inv_freq = 10000^(-2i/128) = exp(-2i * ln(10000)/128)
    float inv = expf(-(float)(2 * i) * (9.210340371976184f / 128.f));
    float th  = (float)s * inv;
    float sn, cs;
    sincosf(th, &sn, &cs);

    size_t base = ((size_t)bh * SEQ + s) * HEAD_DIM + i;
    float q1 = q[base], q2 = q[base + 64];
    q[base]      = q1 * cs - q2 * sn;
    q[base + 64] = q2 * cs + q1 * sn;
    float k1 = k[base], k2 = k[base + 64];
    k[base]      = k1 * cs - k2 * sn;
    k[base + 64] = k2 * cs + k1 * sn;
}

// ============================================================================
// K3: causal flash attention with fused governance bias.
// grid = (S/64, B*HEADS), 256 threads, 64-row Q tile, 64-col KV tiles.
// smem: Q^T[128][68], K^T[128][68], P^T[64][68], V[64][128], row stats.
// ============================================================================
#define BQ   64
#define BKV  64
#define PADQ 68
#define FLASH_SMEM ((128*PADQ*2 + BKV*PADQ + BKV*HEAD_DIM + 3*BQ) * 4)

__global__ __launch_bounds__(256, 1) void flash_kernel(
    const float* __restrict__ q, const float* __restrict__ k, const float* __restrict__ v,
    const float* __restrict__ pm, const float* __restrict__ pol, const float* __restrict__ mw,
    float* __restrict__ attn)
{
    extern __shared__ float smf[];
    float* Qst  = smf;                      // [128][68]  Q^T
    float* Kst  = Qst + 128 * PADQ;         // [128][68]  K^T
    float* Pst  = Kst + 128 * PADQ;         // [64][68]   scores/probs transposed
    float* Vs   = Pst + BKV * PADQ;         // [64][128]
    float* rowm = Vs + BKV * HEAD_DIM;
    float* rowl = rowm + BQ;
    float* rowa = rowl + BQ;

    const int t  = threadIdx.x;
    const int qt = (gridDim.x - 1) - blockIdx.x;   // heavy tiles scheduled first
    const int bh = blockIdx.y;
    const int q0 = qt * BQ;

    const float* qb = q + (size_t)bh * SEQ * HEAD_DIM;
    const float* kb = k + (size_t)bh * SEQ * HEAD_DIM;
    const float* vb = v + (size_t)bh * SEQ * HEAD_DIM;
    const size_t moff = (size_t)bh * SEQ * SEQ;

    // load Q tile, transposed into smem
    for (int fl = t; fl < BQ * 32; fl += 256) {
        int i  = fl >> 5;
        int d0 = (fl & 31) << 2;
        float4 x = *(const float4*)&qb[(size_t)(q0 + i) * HEAD_DIM + d0];
        Qst[(d0 + 0) * PADQ + i] = x.x;
        Qst[(d0 + 1) * PADQ + i] = x.y;
        Qst[(d0 + 2) * PADQ + i] = x.z;
        Qst[(d0 + 3) * PADQ + i] = x.w;
    }
    if (t < BQ) { rowm[t] = -1e30f; rowl[t] = 0.f; }

    const int sr  = (t >> 4) << 2;   // 4 q-rows per thread
    const int sc  = (t & 15) << 2;   // 4 k-cols (scores)
    const int avc = (t & 15) << 3;   // 8 output dims (AV)

    float o[4][8];
#pragma unroll
    for (int i = 0; i < 4; ++i)
#pragma unroll
        for (int j = 0; j < 8; ++j) o[i][j] = 0.f;

    const float scale = 0.08838834764831845f;   // 1/sqrt(128)

    for (int j0 = 0; j0 <= q0; j0 += BKV) {
        __syncthreads();   // previous tile fully consumed
        // load K (transposed) and V tiles
        for (int fl = t; fl < BKV * 32; fl += 256) {
            int j  = fl >> 5;
            int d0 = (fl & 31) << 2;
            float4 x = *(const float4*)&kb[(size_t)(j0 + j) * HEAD_DIM + d0];
            Kst[(d0 + 0) * PADQ + j] = x.x;
            Kst[(d0 + 1) * PADQ + j] = x.y;
            Kst[(d0 + 2) * PADQ + j] = x.z;
            Kst[(d0 + 3) * PADQ + j] = x.w;
            *(float4*)&Vs[j * HEAD_DIM + d0] =
                *(const float4*)&vb[(size_t)(j0 + j) * HEAD_DIM + d0];
        }
        __syncthreads();

        // scores: 4x4 per thread over K-dim 128
        float cc[4][4];
#pragma unroll
        for (int r = 0; r < 4; ++r)
#pragma unroll
            for (int c = 0; c < 4; ++c) cc[r][c] = 0.f;

#pragma unroll 4
        for (int d = 0; d < HEAD_DIM; ++d) {
            float4 a = *(const float4*)&Qst[d * PADQ + sr];
            float4 b = *(const float4*)&Kst[d * PADQ + sc];
            float av[4] = {a.x, a.y, a.z, a.w};
            float bv[4] = {b.x, b.y, b.z, b.w};
#pragma unroll
            for (int r = 0; r < 4; ++r)
#pragma unroll
                for (int c = 0; c < 4; ++c) cc[r][c] += av[r] * bv[c];
        }

        // fused bias + causal mask, write transposed scores
#pragma unroll
        for (int r = 0; r < 4; ++r) {
            int qrow = q0 + sr + r;
            size_t off = moff + (size_t)qrow * SEQ + j0 + sc;
            float4 a4 = *(const float4*)&pm[off];
            float4 b4 = *(const float4*)&pol[off];
            float4 c4 = *(const float4*)&mw[off];
            float av[4] = {a4.x, a4.y, a4.z, a4.w};
            float bv[4] = {b4.x, b4.y, b4.z, b4.w};
            float cv[4] = {c4.x, c4.y, c4.z, c4.w};
#pragma unroll
            for (int c = 0; c < 4; ++c) {
                float sval = cc[r][c] * scale + av[c] * 0.05f + bv[c] * 0.1f
                           + log1pf(cv[c] * 0.1f + 1e-8f);
                if (j0 + sc + c > qrow) sval = -1e30f;
                Pst[(sc + c) * PADQ + (sr + r)] = sval;
            }
        }
        __syncthreads();

        // per-row online softmax (threads 0..63, one row each)
        if (t < BQ) {
            float mold = rowm[t];
            float mx = mold;
#pragma unroll 8
            for (int j = 0; j < BKV; ++j) mx = fmaxf(mx, Pst[j * PADQ + t]);
            float al = __expf(mold - mx);
            float sum = 0.f;
#pragma unroll 8
            for (int j = 0; j < BKV; ++j) {
                float p = __expf(Pst[j * PADQ + t] - mx);
                Pst[j * PADQ + t] = p;
                sum += p;
            }
            rowl[t] = rowl[t] * al + sum;
            rowm[t] = mx;
            rowa[t] = al;
        }
        __syncthreads();

        // rescale accumulators, then P*V
        float al[4] = {rowa[sr], rowa[sr + 1], rowa[sr + 2], rowa[sr + 3]};
#pragma unroll
        for (int r = 0; r < 4; ++r)
#pragma unroll
            for (int j = 0; j < 8; ++j) o[r][j] *= al[r];

#pragma unroll 2
        for (int j = 0; j < BKV; ++j) {
            float4 p  = *(const float4*)&Pst[j * PADQ + sr];
            float4 v0 = *(const float4*)&Vs[j * HEAD_DIM + avc];
            float4 v1 = *(const float4*)&Vs[j * HEAD_DIM + avc + 4];
            float pv[4] = {p.x, p.y, p.z, p.w};
            float vv[8] = {v0.x, v0.y, v0.z, v0.w, v1.x, v1.y, v1.z, v1.w};
#pragma unroll
            for (int r = 0; r < 4; ++r)
#pragma unroll
                for (int d = 0; d < 8; ++d) o[r][d] += pv[r] * vv[d];
        }
    }

    // finalize + write [B, S, H*D]
    const int bb = bh >> 4;
    const int h  = bh & 15;
#pragma unroll
    for (int r = 0; r < 4; ++r) {
        float linv = 1.f / rowl[sr + r];
        int qrow = q0 + sr + r;
        float4 w0 = {o[r][0] * linv, o[r][1] * linv, o[r][2] * linv, o[r][3] * linv};
        float4 w1 = {o[r][4] * linv, o[r][5] * linv, o[r][6] * linv, o[r][7] * linv};
        float* dst = attn + (size_t)(bb * SEQ + qrow) * HIDDEN + h * HEAD_DIM + avc;
        *(float4*)dst       = w0;
        *(float4*)(dst + 4) = w1;
    }
}

// ============================================================================
// host launcher
// ============================================================================
extern "C" void kernel_launch(void* const* d_in, const int* in_sizes, int n_in,
                              void* d_out, int out_size)
{
    const float* x   = (const float*)d_in[0];
    const float* pm  = (const float*)d_in[1];
    const float* pol = (const float*)d_in[2];
    const float* mw  = (const float*)d_in[3];
    const float* Wq  = (const float*)d_in[4];
    const float* Wk  = (const float*)d_in[5];
    const float* Wv  = (const float*)d_in[6];
    const float* Wo  = (const float*)d_in[7];
    const float* bo  = (const float*)d_in[8];
    float* out = (float*)d_out;

    float *gq, *gk, *gv, *ga;
    cudaGetSymbolAddress((void**)&gq, g_q);
    cudaGetSymbolAddress((void**)&gk, g_k);
    cudaGetSymbolAddress((void**)&gv, g_v);
    cudaGetSymbolAddress((void**)&ga, g_attn);

    cudaFuncSetAttribute(flash_kernel,
                         cudaFuncAttributeMaxDynamicSharedMemorySize, FLASH_SMEM);

    // K1: QKV projections, written directly in [B,H,S,D]
    dim3 gqkv(16, 16, 3);
    sgemm2048_kernel<<<gqkv, 256>>>(x, Wq, Wk, Wv, gq, gk, gv, nullptr, 1);

    // K2: RoPE in place on q, k
    int rope_n = BATCH * HEADS * SEQ * 64;
    rope_kernel<<<(rope_n + 255) / 256, 256>>>(gq, gk);

    // K3: fused causal attention with governance bias
    dim3 gfl(SEQ / BQ, BATCH * HEADS);
    flash_kernel<<<gfl, 256, FLASH_SMEM>>>(gq, gk, gv, pm, pol, mw, ga);

    // K4: output projection + bias
    dim3 gout(16, 16, 1);
    sgemm2048_kernel<<<gout, 256>>>(ga, Wo, Wo, Wo, out, out, out, bo, 0);
}

// round 3
// speedup vs baseline: 2.0117x; 2.0117x over previous
#include <cuda_runtime.h>
#include <math.h>
#include <stdint.h>

#define HIDDEN   2048
#define HEADS    16
#define HEAD_DIM 128
#define BATCH    2
#define SEQ      1024
#define MROWS    (BATCH*SEQ)

// ---------------- scratch (allocation-free: device globals) ----------------
__device__ float g_q[BATCH*HEADS*SEQ*HEAD_DIM];
__device__ float g_k[BATCH*HEADS*SEQ*HEAD_DIM];
__device__ float g_v[BATCH*HEADS*SEQ*HEAD_DIM];
__device__ float g_attn[MROWS*HIDDEN];
__device__ float g_xc[MROWS*HIDDEN];        // tf32-rounded x
__device__ float g_wt[4*HIDDEN*HIDDEN];     // transposed tf32-rounded weights [N,K]

// ============================================================================
// helpers
// ============================================================================
__device__ __forceinline__ uint32_t smem_u32(const void* p) {
    uint32_t a;
    asm("{ .reg .u64 t; cvta.to.shared.u64 t, %1; cvt.u32.u64 %0, t; }"
        : "=r"(a) : "l"(p));
    return a;
}
__device__ __forceinline__ float to_tf32(float x) {
    uint32_t u;
    asm("cvt.rna.tf32.f32 %0, %1;" : "=r"(u) : "f"(x));
    return __uint_as_float(u);
}
__device__ __forceinline__ void cpa16(uint32_t s, const void* g) {
    asm volatile("cp.async.cg.shared.global [%0], [%1], 16;" :: "r"(s), "l"(g));
}
#define CPA_COMMIT() asm volatile("cp.async.commit_group;" ::: "memory")
template<int N> __device__ __forceinline__ void cpa_wait() {
    asm volatile("cp.async.wait_group %0;" :: "n"(N) : "memory");
}
__device__ __forceinline__ void mma16n8k8(float* c, const uint32_t* a, const uint32_t* b) {
    asm volatile(
        "mma.sync.aligned.m16n8k8.row.col.f32.tf32.tf32.f32 "
        "{%0,%1,%2,%3}, {%4,%5,%6,%7}, {%8,%9}, {%0,%1,%2,%3};"
        : "+f"(c[0]), "+f"(c[1]), "+f"(c[2]), "+f"(c[3])
        : "r"(a[0]), "r"(a[1]), "r"(a[2]), "r"(a[3]), "r"(b[0]), "r"(b[1]));
}

// ============================================================================
// K0a: weight transpose W[K,N] -> Wt[N,K], tf32-rounded, 4 matrices (z)
// ============================================================================
__global__ void transpose2048(const float* __restrict__ s0, const float* __restrict__ s1,
                              const float* __restrict__ s2, const float* __restrict__ s3,
                              float* __restrict__ dst)
{
    __shared__ float tile[32][33];
    int z = blockIdx.z;
    const float* src = (z == 0) ? s0 : (z == 1) ? s1 : (z == 2) ? s2 : s3;
    float* d = dst + (size_t)z * HIDDEN * HIDDEN;
    int tx = threadIdx.x & 31, ty = threadIdx.x >> 5;
    int x  = blockIdx.x * 32 + tx, y0 = blockIdx.y * 32 + ty;
#pragma unroll
    for (int j = 0; j < 4; ++j)
        tile[ty + j * 8][tx] = to_tf32(src[(size_t)(y0 + j * 8) * HIDDEN + x]);
    __syncthreads();
    int x2 = blockIdx.y * 32 + tx, y2 = blockIdx.x * 32 + ty;
#pragma unroll
    for (int j = 0; j < 4; ++j)
        d[(size_t)(y2 + j * 8) * HIDDEN + x2] = tile[tx][ty + j * 8];
}

// ============================================================================
// K0b: round x to tf32 (elementwise)
// ============================================================================
__global__ void cvt_tf32_kernel(const float* __restrict__ src, float* __restrict__ dst, int n4)
{
    int i = blockIdx.x * blockDim.x + threadIdx.x;
    if (i >= n4) return;
    float4 v = ((const float4*)src)[i];
    v.x = to_tf32(v.x); v.y = to_tf32(v.y); v.z = to_tf32(v.z); v.w = to_tf32(v.w);
    ((float4*)dst)[i] = v;
}

// ============================================================================
// K1/K4: tf32 mma.sync GEMM. C[2048x2048] = A[2048x2048] * Wt[N,K]^T (+bias)
// CTA 128x128, BK=32, 8 warps (warp tile 64x32), cp.async 2-stage.
// A,B operands must be pre-rounded to tf32.
// mode 1: scatter to [B,HEADS,S,HEAD_DIM]; mode 0: row-major + bias.
// ============================================================================
#define BM 128
#define BN 128
#define BK 32
#define PADK 36
#define NKT (HIDDEN / BK)
#define STAGE_FLOATS ((BM + BN) * PADK)
#define GEMM_SMEM (2 * STAGE_FLOATS * 4)

__global__ __launch_bounds__(256, 2) void gemm_mma_kernel(
    const float* __restrict__ A,
    const float* __restrict__ B0, const float* __restrict__ B1, const float* __restrict__ B2,
    float* __restrict__ D0, float* __restrict__ D1, float* __restrict__ D2,
    const float* __restrict__ bias, int mode)
{
    extern __shared__ float sm[];
    const int t    = threadIdx.x;
    const int wid  = t >> 5;
    const int lane = t & 31;
    const int gid  = lane >> 2;   // 0..7
    const int tig  = lane & 3;    // 0..3
    const int z = blockIdx.z;
    const float* __restrict__ B = (z == 0) ? B0 : (z == 1) ? B1 : B2;
    float* __restrict__ D       = (z == 0) ? D0 : (z == 1) ? D1 : D2;
    const int n0 = blockIdx.x * BN;
    const int m0 = blockIdx.y * BM;
    const int wm = (wid & 1) * 64;    // warp m offset
    const int wn = (wid >> 1) * 32;   // warp n offset

    const uint32_t smb = smem_u32(sm);

    // cp.async per-thread mapping: 4 vec4 for A, 4 for B per stage
    const int ldr = t >> 3;          // 0..31 base row
    const int ldc = (t & 7) * 4;     // k offset
    const float* agp = A + (size_t)(m0 + ldr) * HIDDEN + ldc;
    const float* bgp = B + (size_t)(n0 + ldr) * HIDDEN + ldc;
    const uint32_t asb = smb + (uint32_t)(ldr * PADK + ldc) * 4;
    const uint32_t bsb = asb + (uint32_t)(BM * PADK) * 4;

    float acc[4][4][4];
#pragma unroll
    for (int mi = 0; mi < 4; ++mi)
#pragma unroll
        for (int ni = 0; ni < 4; ++ni)
#pragma unroll
            for (int j = 0; j < 4; ++j) acc[mi][ni][j] = 0.f;

    // issue stage for k-tile kt into buffer s
    auto issue = [&](int kt, int s) {
        const uint32_t so = (uint32_t)(s * STAGE_FLOATS) * 4;
        const int ko = kt * BK;
#pragma unroll
        for (int i = 0; i < 4; ++i)
            cpa16(asb + so + (uint32_t)(i * 32 * PADK) * 4, agp + (size_t)i * 32 * HIDDEN + ko);
#pragma unroll
        for (int i = 0; i < 4; ++i)
            cpa16(bsb + so + (uint32_t)(i * 32 * PADK) * 4, bgp + (size_t)i * 32 * HIDDEN + ko);
        CPA_COMMIT();
    };

    issue(0, 0);

    for (int kt = 0; kt < NKT; ++kt) {
        const int s = kt & 1;
        if (kt + 1 < NKT) {
            issue(kt + 1, (kt + 1) & 1);
            cpa_wait<1>();
        } else {
            cpa_wait<0>();
        }
        __syncthreads();

        const uint32_t* Asu = (const uint32_t*)(sm + s * STAGE_FLOATS);
        const uint32_t* Bsu = Asu + BM * PADK;

#pragma unroll
        for (int ks = 0; ks < 4; ++ks) {
            const int k0 = ks * 8;
            uint32_t a[4][4], b[4][2];
#pragma unroll
            for (int mi = 0; mi < 4; ++mi) {
                const int r = wm + mi * 16 + gid;
                a[mi][0] = Asu[r * PADK + k0 + tig];
                a[mi][1] = Asu[(r + 8) * PADK + k0 + tig];
                a[mi][2] = Asu[r * PADK + k0 + tig + 4];
                a[mi][3] = Asu[(r + 8) * PADK + k0 + tig + 4];
            }
#pragma unroll
            for (int ni = 0; ni < 4; ++ni) {
                const int c = wn + ni * 8 + gid;
                b[ni][0] = Bsu[c * PADK + k0 + tig];
                b[ni][1] = Bsu[c * PADK + k0 + tig + 4];
            }
#pragma unroll
            for (int mi = 0; mi < 4; ++mi)
#pragma unroll
                for (int ni = 0; ni < 4; ++ni)
                    mma16n8k8(acc[mi][ni], a[mi], b[ni]);
        }
        __syncthreads();
    }

    // epilogue
#pragma unroll
    for (int mi = 0; mi < 4; ++mi) {
#pragma unroll
        for (int ni = 0; ni < 4; ++ni) {
            const int c = wn + ni * 8 + 2 * tig;       // local n
            const int r0 = wm + mi * 16 + gid;
            const int r1 = r0 + 8;
            float2 v0 = {acc[mi][ni][0], acc[mi][ni][1]};
            float2 v1 = {acc[mi][ni][2], acc[mi][ni][3]};
            if (mode == 0) {
                float2 bb = *(const float2*)&bias[n0 + c];
                v0.x += bb.x; v0.y += bb.y;
                v1.x += bb.x; v1.y += bb.y;
                *(float2*)&D[(size_t)(m0 + r0) * HIDDEN + n0 + c] = v0;
                *(float2*)&D[(size_t)(m0 + r1) * HIDDEN + n0 + c] = v1;
            } else {
                // n block == head h (BN == HEAD_DIM); d = c
                const int h = blockIdx.x;
                int m = m0 + r0;
                int bb0 = m >> 10, s0q = m & 1023;
                *(float2*)&D[(((size_t)(bb0 * HEADS + h) * SEQ + s0q) << 7) + c] = v0;
                m = m0 + r1;
                int bb1 = m >> 10, s1q = m & 1023;
                *(float2*)&D[(((size_t)(bb1 * HEADS + h) * SEQ + s1q) << 7) + c] = v1;
            }
        }
    }
}

// ============================================================================
// K2: in-place RoPE on q and k, layout [B, HEADS, S, HEAD_DIM]
// ============================================================================
__global__ void rope_kernel(float* __restrict__ q, float* __restrict__ k)
{
    int idx = blockIdx.x * blockDim.x + threadIdx.x;
    if (idx >= BATCH * HEADS * SEQ * 64) return;
    int i  = idx & 63;
    int s  = (idx >> 6) & (SEQ - 1);
    int bh = idx >> 16;

    float inv = expf(-(float)(2 * i) * (9.210340371976184f / 128.f));
    float th  = (float)s * inv;
    float sn, cs;
    sincosf(th, &sn, &cs);

    size_t base = ((size_t)bh * SEQ + s) * HEAD_DIM + i;
    float q1 = q[base], q2 = q[base + 64];
    q[base]      = q1 * cs - q2 * sn;
    q[base + 64] = q2 * cs + q1 * sn;
    float k1 = k[base], k2 = k[base + 64];
    k[base]      = k1 * cs - k2 * sn;
    k[base + 64] = k2 * cs + k1 * sn;
}

// ============================================================================
// K3: causal flash attention with fused governance bias
// (epilogue rounds attn to tf32 — it feeds the tf32 output GEMM)
// ============================================================================
#define BQ   64
#define BKV  64
#define PADQ 68
#define FLASH_SMEM ((128*PADQ*2 + BKV*PADQ + BKV*HEAD_DIM + 3*BQ) * 4)

__global__ __launch_bounds__(256, 1) void flash_kernel(
    const float* __restrict__ q, const float* __restrict__ k, const float* __restrict__ v,
    const float* __restrict__ pm, const float* __restrict__ pol, const float* __restrict__ mw,
    float* __restrict__ attn)
{
    extern __shared__ float smf[];
    float* Qst  = smf;
    float* Kst  = Qst + 128 * PADQ;
    float* Pst  = Kst + 128 * PADQ;
    float* Vs   = Pst + BKV * PADQ;
    float* rowm = Vs + BKV * HEAD_DIM;
    float* rowl = rowm + BQ;
    float* rowa = rowl + BQ;

    const int t  = threadIdx.x;
    const int qt = (gridDim.x - 1) - blockIdx.x;
    const int bh = blockIdx.y;
    const int q0 = qt * BQ;

    const float* qb = q + (size_t)bh * SEQ * HEAD_DIM;
    const float* kb = k + (size_t)bh * SEQ * HEAD_DIM;
    const float* vb = v + (size_t)bh * SEQ * HEAD_DIM;
    const size_t moff = (size_t)bh * SEQ * SEQ;

    for (int fl = t; fl < BQ * 32; fl += 256) {
        int i  = fl >> 5;
        int d0 = (fl & 31) << 2;
        float4 x = *(const float4*)&qb[(size_t)(q0 + i) * HEAD_DIM + d0];
        Qst[(d0 + 0) * PADQ + i] = x.x;
        Qst[(d0 + 1) * PADQ + i] = x.y;
        Qst[(d0 + 2) * PADQ + i] = x.z;
        Qst[(d0 + 3) * PADQ + i] = x.w;
    }
    if (t < BQ) { rowm[t] = -1e30f; rowl[t] = 0.f; }

    const int sr  = (t >> 4) << 2;
    const int sc  = (t & 15) << 2;
    const int avc = (t & 15) << 3;

    float o[4][8];
#pragma unroll
    for (int i = 0; i < 4; ++i)
#pragma unroll
        for (int j = 0; j < 8; ++j) o[i][j] = 0.f;

    const float scale = 0.08838834764831845f;

    for (int j0 = 0; j0 <= q0; j0 += BKV) {
        __syncthreads();
        for (int fl = t; fl < BKV * 32; fl += 256) {
            int j  = fl >> 5;
            int d0 = (fl & 31) << 2;
            float4 x = *(const float4*)&kb[(size_t)(j0 + j) * HEAD_DIM + d0];
            Kst[(d0 + 0) * PADQ + j] = x.x;
            Kst[(d0 + 1) * PADQ + j] = x.y;
            Kst[(d0 + 2) * PADQ + j] = x.z;
            Kst[(d0 + 3) * PADQ + j] = x.w;
            *(float4*)&Vs[j * HEAD_DIM + d0] =
                *(const float4*)&vb[(size_t)(j0 + j) * HEAD_DIM + d0];
        }
        __syncthreads();

        float cc[4][4];
#pragma unroll
        for (int r = 0; r < 4; ++r)
#pragma unroll
            for (int c = 0; c < 4; ++c) cc[r][c] = 0.f;

#pragma unroll 4
        for (int d = 0; d < HEAD_DIM; ++d) {
            float4 a = *(const float4*)&Qst[d * PADQ + sr];
            float4 b = *(const float4*)&Kst[d * PADQ + sc];
            float av[4] = {a.x, a.y, a.z, a.w};
            float bv[4] = {b.x, b.y, b.z, b.w};
#pragma unroll
            for (int r = 0; r < 4; ++r)
#pragma unroll
                for (int c = 0; c < 4; ++c) cc[r][c] += av[r] * bv[c];
        }

#pragma unroll
        for (int r = 0; r < 4; ++r) {
            int qrow = q0 + sr + r;
            size_t off = moff + (size_t)qrow * SEQ + j0 + sc;
            float4 a4 = *(const float4*)&pm[off];
            float4 b4 = *(const float4*)&pol[off];
            float4 c4 = *(const float4*)&mw[off];
            float av[4] = {a4.x, a4.y, a4.z, a4.w};
            float bv[4] = {b4.x, b4.y, b4.z, b4.w};
            float cv[4] = {c4.x, c4.y, c4.z, c4.w};
#pragma unroll
            for (int c = 0; c < 4; ++c) {
                float sval = cc[r][c] * scale + av[c] * 0.05f + bv[c] * 0.1f
                           + log1pf(cv[c] * 0.1f + 1e-8f);
                if (j0 + sc + c > qrow) sval = -1e30f;
                Pst[(sc + c) * PADQ + (sr + r)] = sval;
            }
        }
        __syncthreads();

        if (t < BQ) {
            float mold = rowm[t];
            float mx = mold;
#pragma unroll 8
            for (int j = 0; j < BKV; ++j) mx = fmaxf(mx, Pst[j * PADQ + t]);
            float al = __expf(mold - mx);
            float sum = 0.f;
#pragma unroll 8
            for (int j = 0; j < BKV; ++j) {
                float p = __expf(Pst[j * PADQ + t] - mx);
                Pst[j * PADQ + t] = p;
                sum += p;
            }
            rowl[t] = rowl[t] * al + sum;
            rowm[t] = mx;
            rowa[t] = al;
        }
        __syncthreads();

        float al[4] = {rowa[sr], rowa[sr + 1], rowa[sr + 2], rowa[sr + 3]};
#pragma unroll
        for (int r = 0; r < 4; ++r)
#pragma unroll
            for (int j = 0; j < 8; ++j) o[r][j] *= al[r];

#pragma unroll 2
        for (int j = 0; j < BKV; ++j) {
            float4 p  = *(const float4*)&Pst[j * PADQ + sr];
            float4 v0 = *(const float4*)&Vs[j * HEAD_DIM + avc];
            float4 v1 = *(const float4*)&Vs[j * HEAD_DIM + avc + 4];
            float pv[4] = {p.x, p.y, p.z, p.w};
            float vv[8] = {v0.x, v0.y, v0.z, v0.w, v1.x, v1.y, v1.z, v1.w};
#pragma unroll
            for (int r = 0; r < 4; ++r)
#pragma unroll
                for (int d = 0; d < 8; ++d) o[r][d] += pv[r] * vv[d];
        }
    }

    const int bb = bh >> 4;
    const int h  = bh & 15;
#pragma unroll
    for (int r = 0; r < 4; ++r) {
        float linv = 1.f / rowl[sr + r];
        int qrow = q0 + sr + r;
        float4 w0 = {to_tf32(o[r][0] * linv), to_tf32(o[r][1] * linv),
                     to_tf32(o[r][2] * linv), to_tf32(o[r][3] * linv)};
        float4 w1 = {to_tf32(o[r][4] * linv), to_tf32(o[r][5] * linv),
                     to_tf32(o[r][6] * linv), to_tf32(o[r][7] * linv)};
        float* dst = attn + (size_t)(bb * SEQ + qrow) * HIDDEN + h * HEAD_DIM + avc;
        *(float4*)dst       = w0;
        *(float4*)(dst + 4) = w1;
    }
}

// ============================================================================
// host launcher
// ============================================================================
extern "C" void kernel_launch(void* const* d_in, const int* in_sizes, int n_in,
                              void* d_out, int out_size)
{
    const float* x   = (const float*)d_in[0];
    const float* pm  = (const float*)d_in[1];
    const float* pol = (const float*)d_in[2];
    const float* mw  = (const float*)d_in[3];
    const float* Wq  = (const float*)d_in[4];
    const float* Wk  = (const float*)d_in[5];
    const float* Wv  = (const float*)d_in[6];
    const float* Wo  = (const float*)d_in[7];
    const float* bo  = (const float*)d_in[8];
    float* out = (float*)d_out;

    float *gq, *gk, *gv, *ga, *gw, *gx;
    cudaGetSymbolAddress((void**)&gq, g_q);
    cudaGetSymbolAddress((void**)&gk, g_k);
    cudaGetSymbolAddress((void**)&gv, g_v);
    cudaGetSymbolAddress((void**)&ga, g_attn);
    cudaGetSymbolAddress((void**)&gw, g_wt);
    cudaGetSymbolAddress((void**)&gx, g_xc);

    cudaFuncSetAttribute(flash_kernel,
                         cudaFuncAttributeMaxDynamicSharedMemorySize, FLASH_SMEM);
    cudaFuncSetAttribute(gemm_mma_kernel,
                         cudaFuncAttributeMaxDynamicSharedMemorySize, GEMM_SMEM);

    float* wtq = gw;
    float* wtk = gw + (size_t)HIDDEN * HIDDEN;
    float* wtv = gw + 2 * (size_t)HIDDEN * HIDDEN;
    float* wto = gw + 3 * (size_t)HIDDEN * HIDDEN;

    // K0: transpose + tf32-round weights; round x
    transpose2048<<<dim3(64, 64, 4), 256>>>(Wq, Wk, Wv, Wo, gw);
    cvt_tf32_kernel<<<(MROWS * HIDDEN / 4 + 255) / 256, 256>>>(x, gx, MROWS * HIDDEN / 4);

    // K1: QKV projections (tf32 mma.sync), written directly in [B,H,S,D]
    gemm_mma_kernel<<<dim3(HIDDEN / BN, MROWS / BM, 3), 256, GEMM_SMEM>>>(
        gx, wtq, wtk, wtv, gq, gk, gv, nullptr, 1);

    // K2: RoPE in place on q, k
    int rope_n = BATCH * HEADS * SEQ * 64;
    rope_kernel<<<(rope_n + 255) / 256, 256>>>(gq, gk);

    // K3: fused causal attention with governance bias
    dim3 gfl(SEQ / BQ, BATCH * HEADS);
    flash_kernel<<<gfl, 256, FLASH_SMEM>>>(gq, gk, gv, pm, pol, mw, ga);

    // K4: output projection + bias (tf32 mma.sync)
    gemm_mma_kernel<<<dim3(HIDDEN / BN, MROWS / BM, 1), 256, GEMM_SMEM>>>(
        ga, wto, wto, wto, out, out, out, bo, 0);
}

// round 4
// speedup vs baseline: 3.1584x; 1.5700x over previous
#include <cuda_runtime.h>
#include <math.h>
#include <stdint.h>

#define HIDDEN   2048
#define HEADS    16
#define HEAD_DIM 128
#define BATCH    2
#define SEQ      1024
#define MROWS    (BATCH*SEQ)

// ---------------- scratch (allocation-free: device globals) ----------------
__device__ float g_q[BATCH*HEADS*SEQ*HEAD_DIM];
__device__ float g_k[BATCH*HEADS*SEQ*HEAD_DIM];
__device__ float g_v[BATCH*HEADS*SEQ*HEAD_DIM];
__device__ float g_attn[MROWS*HIDDEN];
__device__ float g_xc[MROWS*HIDDEN];        // tf32-rounded x
__device__ float g_wc[4*HIDDEN*HIDDEN];     // tf32-rounded weights, original [K,N] layout

// ============================================================================
// helpers
// ============================================================================
__device__ __forceinline__ uint32_t smem_u32(const void* p) {
    uint32_t a;
    asm("{ .reg .u64 t; cvta.to.shared.u64 t, %1; cvt.u32.u64 %0, t; }"
        : "=r"(a) : "l"(p));
    return a;
}
__device__ __forceinline__ float to_tf32(float x) {
    uint32_t u;
    asm("cvt.rna.tf32.f32 %0, %1;" : "=r"(u) : "f"(x));
    return __uint_as_float(u);
}
__device__ __forceinline__ void cpa16(uint32_t s, const void* g) {
    asm volatile("cp.async.cg.shared.global [%0], [%1], 16;" :: "r"(s), "l"(g));
}
#define CPA_COMMIT() asm volatile("cp.async.commit_group;" ::: "memory")
template<int N> __device__ __forceinline__ void cpa_wait() {
    asm volatile("cp.async.wait_group %0;" :: "n"(N) : "memory");
}
__device__ __forceinline__ void mma16n8k8(float* c, const uint32_t* a, const uint32_t* b) {
    asm volatile(
        "mma.sync.aligned.m16n8k8.row.col.f32.tf32.tf32.f32 "
        "{%0,%1,%2,%3}, {%4,%5,%6,%7}, {%8,%9}, {%0,%1,%2,%3};"
        : "+f"(c[0]), "+f"(c[1]), "+f"(c[2]), "+f"(c[3])
        : "r"(a[0]), "r"(a[1]), "r"(a[2]), "r"(a[3]), "r"(b[0]), "r"(b[1]));
}

// 2^x via FMA-pipe polynomial (no MUFU). |rel err| < ~2e-6 on valid range.
__device__ __forceinline__ float exp2c(float x) {
    x = fmaxf(x, -126.f);
    float fl = floorf(x);
    float f  = x - fl;
    int   i  = (int)fl;
    float r = 1.52527338e-5f;
    r = fmaf(r, f, 1.54035304e-4f);
    r = fmaf(r, f, 1.33335581e-3f);
    r = fmaf(r, f, 9.61812911e-3f);
    r = fmaf(r, f, 5.55041087e-2f);
    r = fmaf(r, f, 2.40226507e-1f);
    r = fmaf(r, f, 6.93147181e-1f);
    r = fmaf(r, f, 1.0f);
    return r * __int_as_float((i + 127) << 23);
}
// log2(1+u) for u in [0, ~0.101] via deg-7 series, abs err < 2e-9
__device__ __forceinline__ float log2p_small(float u) {
    float r = 0.14285714f;
    r = fmaf(r, u, -0.16666667f);
    r = fmaf(r, u, 0.2f);
    r = fmaf(r, u, -0.25f);
    r = fmaf(r, u, 0.33333333f);
    r = fmaf(r, u, -0.5f);
    r = fmaf(r, u, 1.0f);
    return r * u * 1.4426950408889634f;
}

// ============================================================================
// K0: elementwise tf32 rounding
// ============================================================================
__global__ void cvt_tf32_kernel(const float* __restrict__ src, float* __restrict__ dst, int n4)
{
    int i = blockIdx.x * blockDim.x + threadIdx.x;
    if (i >= n4) return;
    float4 v = ((const float4*)src)[i];
    v.x = to_tf32(v.x); v.y = to_tf32(v.y); v.z = to_tf32(v.z); v.w = to_tf32(v.w);
    ((float4*)dst)[i] = v;
}

// ============================================================================
// K1/K4: tf32 mma.sync GEMM. C = A[2048x2048] * W[K,N] (+bias)
// CTA 128x128, BK=32, 8 warps (warp tile 64x32), cp.async 2-stage.
// B tiles loaded K-major directly (no transpose needed).
// ============================================================================
#define BM 128
#define BN 128
#define BK 32
#define PADK 36
#define PADN 136
#define ASTAGE (BM*PADK)
#define BSTAGE (BK*PADN)
#define NKT (HIDDEN / BK)
#define STAGE_FLOATS (ASTAGE + BSTAGE)
#define GEMM_SMEM (2 * STAGE_FLOATS * 4)

__global__ __launch_bounds__(256, 2) void gemm_mma_kernel(
    const float* __restrict__ A,
    const float* __restrict__ B0, const float* __restrict__ B1, const float* __restrict__ B2,
    float* __restrict__ D0, float* __restrict__ D1, float* __restrict__ D2,
    const float* __restrict__ bias, int mode)
{
    extern __shared__ float sm[];
    const int t    = threadIdx.x;
    const int wid  = t >> 5;
    const int lane = t & 31;
    const int gid  = lane >> 2;
    const int tig  = lane & 3;
    const int z = blockIdx.z;
    const float* __restrict__ B = (z == 0) ? B0 : (z == 1) ? B1 : B2;
    float* __restrict__ D       = (z == 0) ? D0 : (z == 1) ? D1 : D2;
    const int n0 = blockIdx.x * BN;
    const int m0 = blockIdx.y * BM;
    const int wm = (wid & 1) * 64;
    const int wn = (wid >> 1) * 32;

    const uint32_t smb = smem_u32(sm);

    // A cp.async mapping (rows m, k-contig)
    const int ldr = t >> 3;
    const int ldc = (t & 7) * 4;
    const float* agp = A + (size_t)(m0 + ldr) * HIDDEN + ldc;
    const uint32_t asb = smb + (uint32_t)(ldr * PADK + ldc) * 4;
    // B cp.async mapping (rows k, n-contig)
    const int br = t >> 5;           // 0..7 (+8 per iter, 32 rows)
    const int bc = (t & 31) * 4;
    const float* bgp = B + (size_t)br * HIDDEN + n0 + bc;
    const uint32_t bsb = smb + (uint32_t)(ASTAGE + br * PADN + bc) * 4;

    float acc[4][4][4];
#pragma unroll
    for (int mi = 0; mi < 4; ++mi)
#pragma unroll
        for (int ni = 0; ni < 4; ++ni)
#pragma unroll
            for (int j = 0; j < 4; ++j) acc[mi][ni][j] = 0.f;

    auto issue = [&](int kt, int s) {
        const uint32_t so = (uint32_t)(s * STAGE_FLOATS) * 4;
        const int ko = kt * BK;
#pragma unroll
        for (int i = 0; i < 4; ++i)
            cpa16(asb + so + (uint32_t)(i * 32 * PADK) * 4, agp + (size_t)i * 32 * HIDDEN + ko);
#pragma unroll
        for (int i = 0; i < 4; ++i)
            cpa16(bsb + so + (uint32_t)(i * 8 * PADN) * 4, bgp + (size_t)(i * 8 + ko) * HIDDEN);
        CPA_COMMIT();
    };

    issue(0, 0);

    for (int kt = 0; kt < NKT; ++kt) {
        const int s = kt & 1;
        if (kt + 1 < NKT) {
            issue(kt + 1, (kt + 1) & 1);
            cpa_wait<1>();
        } else {
            cpa_wait<0>();
        }
        __syncthreads();

        const uint32_t* Asu = (const uint32_t*)(sm + s * STAGE_FLOATS);
        const uint32_t* Bsu = Asu + ASTAGE;

#pragma unroll
        for (int ks = 0; ks < 4; ++ks) {
            const int k0 = ks * 8;
            uint32_t a[4][4], b[4][2];
#pragma unroll
            for (int mi = 0; mi < 4; ++mi) {
                const int r = wm + mi * 16 + gid;
                a[mi][0] = Asu[r * PADK + k0 + tig];
                a[mi][1] = Asu[(r + 8) * PADK + k0 + tig];
                a[mi][2] = Asu[r * PADK + k0 + tig + 4];
                a[mi][3] = Asu[(r + 8) * PADK + k0 + tig + 4];
            }
#pragma unroll
            for (int ni = 0; ni < 4; ++ni) {
                const int c = wn + ni * 8 + gid;
                b[ni][0] = Bsu[(k0 + tig) * PADN + c];
                b[ni][1] = Bsu[(k0 + tig + 4) * PADN + c];
            }
#pragma unroll
            for (int mi = 0; mi < 4; ++mi)
#pragma unroll
                for (int ni = 0; ni < 4; ++ni)
                    mma16n8k8(acc[mi][ni], a[mi], b[ni]);
        }
        __syncthreads();
    }

#pragma unroll
    for (int mi = 0; mi < 4; ++mi) {
#pragma unroll
        for (int ni = 0; ni < 4; ++ni) {
            const int c = wn + ni * 8 + 2 * tig;
            const int r0 = wm + mi * 16 + gid;
            const int r1 = r0 + 8;
            float2 v0 = {acc[mi][ni][0], acc[mi][ni][1]};
            float2 v1 = {acc[mi][ni][2], acc[mi][ni][3]};
            if (mode == 0) {
                float2 bb = *(const float2*)&bias[n0 + c];
                v0.x += bb.x; v0.y += bb.y;
                v1.x += bb.x; v1.y += bb.y;
                *(float2*)&D[(size_t)(m0 + r0) * HIDDEN + n0 + c] = v0;
                *(float2*)&D[(size_t)(m0 + r1) * HIDDEN + n0 + c] = v1;
            } else {
                const int h = blockIdx.x;
                int m = m0 + r0;
                int bb0 = m >> 10, s0q = m & 1023;
                *(float2*)&D[(((size_t)(bb0 * HEADS + h) * SEQ + s0q) << 7) + c] = v0;
                m = m0 + r1;
                int bb1 = m >> 10, s1q = m & 1023;
                *(float2*)&D[(((size_t)(bb1 * HEADS + h) * SEQ + s1q) << 7) + c] = v1;
            }
        }
    }
}

// ============================================================================
// K2: RoPE in place on q,k; k,v rounded to tf32 (flash MMA operands)
// ============================================================================
__global__ void rope_kernel(float* __restrict__ q, float* __restrict__ k, float* __restrict__ v)
{
    int idx = blockIdx.x * blockDim.x + threadIdx.x;
    if (idx >= BATCH * HEADS * SEQ * 64) return;
    int i  = idx & 63;
    int s  = (idx >> 6) & (SEQ - 1);
    int bh = idx >> 16;

    float inv = expf(-(float)(2 * i) * (9.210340371976184f / 128.f));
    float th  = (float)s * inv;
    float sn, cs;
    sincosf(th, &sn, &cs);

    size_t base = ((size_t)bh * SEQ + s) * HEAD_DIM + i;
    float q1 = q[base], q2 = q[base + 64];
    q[base]      = q1 * cs - q2 * sn;        // full fp32 (split in flash)
    q[base + 64] = q2 * cs + q1 * sn;
    float k1 = k[base], k2 = k[base + 64];
    k[base]      = to_tf32(k1 * cs - k2 * sn);
    k[base + 64] = to_tf32(k2 * cs + k1 * sn);
    v[base]      = to_tf32(v[base]);
    v[base + 64] = to_tf32(v[base + 64]);
}

// ============================================================================
// K3: causal flash attention, tf32 mma.sync, fused bias, log2-domain softmax.
// CTA: 64 q-rows, 8 warps (4m x 2n). K/V double-buffered cp.async.
// Q split hi/lo (error-free Q side). grid = (16, 32).
// ============================================================================
#define FPADD 132
#define FPADV 136
#define FPADP 68
#define OQH  0
#define OQL  8448
#define OKS  16896
#define OVS  33792
#define OPS  51200
#define ORM  55552
#define ORL  55616
#define ORDM 55680
#define ORDS 55808
#define FLASH_FLOATS 55936
#define FLASH_SMEM (FLASH_FLOATS * 4)

__global__ __launch_bounds__(256, 1) void flash_kernel(
    const float* __restrict__ q, const float* __restrict__ k, const float* __restrict__ v,
    const float* __restrict__ pm, const float* __restrict__ pol, const float* __restrict__ mw,
    float* __restrict__ attn)
{
    extern __shared__ float smf[];
    const uint32_t smb = smem_u32(smf);

    const int t    = threadIdx.x;
    const int wid  = t >> 5;
    const int lane = t & 31;
    const int gid  = lane >> 2;
    const int tig  = lane & 3;
    const int wm   = (wid & 3) * 16;     // warp q-row offset (16 rows)
    const int wni  = wid >> 2;           // 0/1
    const int wn   = wni * 32;           // QK col offset
    const int wd   = wni * 64;           // PV dim offset

    const int qt = (gridDim.x - 1) - blockIdx.x;   // heavy first
    const int bh = blockIdx.y;
    const int q0 = qt * 64;

    const float* qb = q + (size_t)bh * SEQ * HEAD_DIM;
    const float* kb = k + (size_t)bh * SEQ * HEAD_DIM;
    const float* vb = v + (size_t)bh * SEQ * HEAD_DIM;
    const size_t moff = (size_t)bh * SEQ * SEQ;

    // ---- load Q tile, split hi/lo tf32 ----
    for (int idx = t; idx < 64 * 32; idx += 256) {
        int r  = idx >> 5;
        int c4 = (idx & 31) * 4;
        float4 x = *(const float4*)&qb[(size_t)(q0 + r) * HEAD_DIM + c4];
        float* qh = smf + OQH + r * FPADD + c4;
        float* ql = smf + OQL + r * FPADD + c4;
        float h0 = to_tf32(x.x); qh[0] = h0; ql[0] = to_tf32(x.x - h0);
        float h1 = to_tf32(x.y); qh[1] = h1; ql[1] = to_tf32(x.y - h1);
        float h2 = to_tf32(x.z); qh[2] = h2; ql[2] = to_tf32(x.z - h2);
        float h3 = to_tf32(x.w); qh[3] = h3; ql[3] = to_tf32(x.w - h3);
    }
    if (t < 64) { smf[ORM + t] = -1e30f; smf[ORL + t] = 0.f; }

    // KV producer
    auto issueKV = [&](int jt, int s) {
        const int j0 = jt * 64;
#pragma unroll
        for (int i = 0; i < 8; ++i) {
            int idx = i * 256 + t;
            int r  = idx >> 5;
            int c4 = (idx & 31) * 4;
            const float* kg = &kb[(size_t)(j0 + r) * HEAD_DIM + c4];
            const float* vg = &vb[(size_t)(j0 + r) * HEAD_DIM + c4];
            cpa16(smb + (uint32_t)(OKS + s * 8448 + r * FPADD + c4) * 4, kg);
            cpa16(smb + (uint32_t)(OVS + s * 8704 + r * FPADV + c4) * 4, vg);
        }
        CPA_COMMIT();
    };

    issueKV(0, 0);

    const float SC2  = 0.08838834764831845f * 1.4426950408889634f;
    const float CPM  = 0.05f * 1.4426950408889634f;
    const float CPO  = 0.1f  * 1.4426950408889634f;

    const int row0  = wm + gid;
    const int row1  = row0 + 8;
    const int grow0 = q0 + row0;
    const int grow1 = q0 + row1;

    float acc_o[8][4];
#pragma unroll
    for (int ni = 0; ni < 8; ++ni)
#pragma unroll
        for (int j = 0; j < 4; ++j) acc_o[ni][j] = 0.f;

    for (int jt = 0; jt <= qt; ++jt) {
        if (jt < qt) { issueKV(jt + 1, (jt + 1) & 1); cpa_wait<1>(); }
        else         { cpa_wait<0>(); }
        __syncthreads();   // #1: KV ready; prev-tile Ps consumed; rowm updated

        const float* Kb = smf + OKS + (jt & 1) * 8448;
        const float* Vb = smf + OVS + (jt & 1) * 8704;
        const int j0c = jt * 64;

        // ---- QK^T (split-Q tf32 mma) ----
        float accs[4][4];
#pragma unroll
        for (int ni = 0; ni < 4; ++ni)
#pragma unroll
            for (int j = 0; j < 4; ++j) accs[ni][j] = 0.f;

#pragma unroll
        for (int ks = 0; ks < 16; ++ks) {
            const int k0 = ks * 8;
            uint32_t ah[4], al[4], b[4][2];
            const uint32_t* Qh = (const uint32_t*)(smf + OQH);
            const uint32_t* Ql = (const uint32_t*)(smf + OQL);
            ah[0] = Qh[row0 * FPADD + k0 + tig];
            ah[1] = Qh[row1 * FPADD + k0 + tig];
            ah[2] = Qh[row0 * FPADD + k0 + tig + 4];
            ah[3] = Qh[row1 * FPADD + k0 + tig + 4];
            al[0] = Ql[row0 * FPADD + k0 + tig];
            al[1] = Ql[row1 * FPADD + k0 + tig];
            al[2] = Ql[row0 * FPADD + k0 + tig + 4];
            al[3] = Ql[row1 * FPADD + k0 + tig + 4];
            const uint32_t* Ku = (const uint32_t*)Kb;
#pragma unroll
            for (int ni = 0; ni < 4; ++ni) {
                const int c = wn + ni * 8 + gid;
                b[ni][0] = Ku[c * FPADD + k0 + tig];
                b[ni][1] = Ku[c * FPADD + k0 + tig + 4];
            }
#pragma unroll
            for (int ni = 0; ni < 4; ++ni) {
                mma16n8k8(accs[ni], ah, b[ni]);
                mma16n8k8(accs[ni], al, b[ni]);
            }
        }

        // ---- bias + causal + row max (log2 domain) ----
        const bool diag = (jt == qt);
        float ml0 = -1e30f, ml1 = -1e30f;
        const size_t mr0 = moff + (size_t)grow0 * SEQ + j0c;
        const size_t mr1 = moff + (size_t)grow1 * SEQ + j0c;
#pragma unroll
        for (int ni = 0; ni < 4; ++ni) {
            const int cl = wn + ni * 8 + 2 * tig;
            float2 a0 = *(const float2*)&pm[mr0 + cl];
            float2 b0 = *(const float2*)&pol[mr0 + cl];
            float2 c0 = *(const float2*)&mw[mr0 + cl];
            float2 a1 = *(const float2*)&pm[mr1 + cl];
            float2 b1 = *(const float2*)&pol[mr1 + cl];
            float2 c1 = *(const float2*)&mw[mr1 + cl];
            float s0 = fmaf(accs[ni][0], SC2, fmaf(a0.x, CPM, fmaf(b0.x, CPO, log2p_small(fmaf(c0.x, 0.1f, 1e-8f)))));
            float s1 = fmaf(accs[ni][1], SC2, fmaf(a0.y, CPM, fmaf(b0.y, CPO, log2p_small(fmaf(c0.y, 0.1f, 1e-8f)))));
            float s2 = fmaf(accs[ni][2], SC2, fmaf(a1.x, CPM, fmaf(b1.x, CPO, log2p_small(fmaf(c1.x, 0.1f, 1e-8f)))));
            float s3 = fmaf(accs[ni][3], SC2, fmaf(a1.y, CPM, fmaf(b1.y, CPO, log2p_small(fmaf(c1.y, 0.1f, 1e-8f)))));
            if (diag) {
                if (cl     > row0) s0 = -1e30f;
                if (cl + 1 > row0) s1 = -1e30f;
                if (cl     > row1) s2 = -1e30f;
                if (cl + 1 > row1) s3 = -1e30f;
            }
            accs[ni][0] = s0; accs[ni][1] = s1; accs[ni][2] = s2; accs[ni][3] = s3;
            ml0 = fmaxf(ml0, fmaxf(s0, s1));
            ml1 = fmaxf(ml1, fmaxf(s2, s3));
        }
#pragma unroll
        for (int o = 1; o < 4; o <<= 1) {
            ml0 = fmaxf(ml0, __shfl_xor_sync(0xffffffffu, ml0, o));
            ml1 = fmaxf(ml1, __shfl_xor_sync(0xffffffffu, ml1, o));
        }
        if (tig == 0) {
            smf[ORDM + wni * 64 + row0] = ml0;
            smf[ORDM + wni * 64 + row1] = ml1;
        }
        float mold0 = smf[ORM + row0];
        float mold1 = smf[ORM + row1];
        __syncthreads();   // #2: redm ready

        float mn0 = fmaxf(mold0, fmaxf(smf[ORDM + row0], smf[ORDM + 64 + row0]));
        float mn1 = fmaxf(mold1, fmaxf(smf[ORDM + row1], smf[ORDM + 64 + row1]));
        float al0 = exp2c(mold0 - mn0);
        float al1 = exp2c(mold1 - mn1);

        float sum0 = 0.f, sum1 = 0.f;
#pragma unroll
        for (int ni = 0; ni < 4; ++ni) {
            const int cl = wn + ni * 8 + 2 * tig;
            float p0 = exp2c(accs[ni][0] - mn0);
            float p1 = exp2c(accs[ni][1] - mn0);
            float p2 = exp2c(accs[ni][2] - mn1);
            float p3 = exp2c(accs[ni][3] - mn1);
            sum0 += p0 + p1;
            sum1 += p2 + p3;
            smf[OPS + row0 * FPADP + cl]     = to_tf32(p0);
            smf[OPS + row0 * FPADP + cl + 1] = to_tf32(p1);
            smf[OPS + row1 * FPADP + cl]     = to_tf32(p2);
            smf[OPS + row1 * FPADP + cl + 1] = to_tf32(p3);
        }
#pragma unroll
        for (int o = 1; o < 4; o <<= 1) {
            sum0 += __shfl_xor_sync(0xffffffffu, sum0, o);
            sum1 += __shfl_xor_sync(0xffffffffu, sum1, o);
        }
        if (tig == 0) {
            smf[ORDS + wni * 64 + row0] = sum0;
            smf[ORDS + wni * 64 + row1] = sum1;
        }
        // rescale output accumulators
#pragma unroll
        for (int ni = 0; ni < 8; ++ni) {
            acc_o[ni][0] *= al0; acc_o[ni][1] *= al0;
            acc_o[ni][2] *= al1; acc_o[ni][3] *= al1;
        }
        __syncthreads();   // #3: Ps + reds ready

        if (t < 64) {
            float mo = smf[ORM + t];
            float mn = fmaxf(mo, fmaxf(smf[ORDM + t], smf[ORDM + 64 + t]));
            float a  = exp2c(mo - mn);
            smf[ORL + t] = smf[ORL + t] * a + smf[ORDS + t] + smf[ORDS + 64 + t];
            smf[ORM + t] = mn;
        }

        // ---- P·V (tf32 mma) ----
        const uint32_t* Pu = (const uint32_t*)(smf + OPS);
        const uint32_t* Vu = (const uint32_t*)Vb;
#pragma unroll
        for (int ks = 0; ks < 8; ++ks) {
            const int k0 = ks * 8;
            uint32_t a[4], b[8][2];
            a[0] = Pu[row0 * FPADP + k0 + tig];
            a[1] = Pu[row1 * FPADP + k0 + tig];
            a[2] = Pu[row0 * FPADP + k0 + tig + 4];
            a[3] = Pu[row1 * FPADP + k0 + tig + 4];
#pragma unroll
            for (int ni = 0; ni < 8; ++ni) {
                const int c = wd + ni * 8 + gid;
                b[ni][0] = Vu[(k0 + tig) * FPADV + c];
                b[ni][1] = Vu[(k0 + tig + 4) * FPADV + c];
            }
#pragma unroll
            for (int ni = 0; ni < 8; ++ni)
                mma16n8k8(acc_o[ni], a, b[ni]);
        }
    }

    __syncthreads();
    const float l0 = 1.f / smf[ORL + row0];
    const float l1 = 1.f / smf[ORL + row1];
    const int bb = bh >> 4;
    const int h  = bh & 15;
    float* o0 = attn + ((size_t)(bb * SEQ + grow0)) * HIDDEN + h * HEAD_DIM;
    float* o1 = attn + ((size_t)(bb * SEQ + grow1)) * HIDDEN + h * HEAD_DIM;
#pragma unroll
    for (int ni = 0; ni < 8; ++ni) {
        const int d = wd + ni * 8 + 2 * tig;
        float2 w0 = {to_tf32(acc_o[ni][0] * l0), to_tf32(acc_o[ni][1] * l0)};
        float2 w1 = {to_tf32(acc_o[ni][2] * l1), to_tf32(acc_o[ni][3] * l1)};
        *(float2*)(o0 + d) = w0;
        *(float2*)(o1 + d) = w1;
    }
}

// ============================================================================
// host launcher
// ============================================================================
extern "C" void kernel_launch(void* const* d_in, const int* in_sizes, int n_in,
                              void* d_out, int out_size)
{
    const float* x   = (const float*)d_in[0];
    const float* pm  = (const float*)d_in[1];
    const float* pol = (const float*)d_in[2];
    const float* mw  = (const float*)d_in[3];
    const float* Wq  = (const float*)d_in[4];
    const float* Wk  = (const float*)d_in[5];
    const float* Wv  = (const float*)d_in[6];
    const float* Wo  = (const float*)d_in[7];
    const float* bo  = (const float*)d_in[8];
    float* out = (float*)d_out;

    float *gq, *gk, *gv, *ga, *gw, *gx;
    cudaGetSymbolAddress((void**)&gq, g_q);
    cudaGetSymbolAddress((void**)&gk, g_k);
    cudaGetSymbolAddress((void**)&gv, g_v);
    cudaGetSymbolAddress((void**)&ga, g_attn);
    cudaGetSymbolAddress((void**)&gw, g_wc);
    cudaGetSymbolAddress((void**)&gx, g_xc);

    cudaFuncSetAttribute(flash_kernel,
                         cudaFuncAttributeMaxDynamicSharedMemorySize, FLASH_SMEM);
    cudaFuncSetAttribute(gemm_mma_kernel,
                         cudaFuncAttributeMaxDynamicSharedMemorySize, GEMM_SMEM);

    float* wcq = gw;
    float* wck = gw + (size_t)HIDDEN * HIDDEN;
    float* wcv = gw + 2 * (size_t)HIDDEN * HIDDEN;
    float* wco = gw + 3 * (size_t)HIDDEN * HIDDEN;

    const int n4 = HIDDEN * HIDDEN / 4;
    cvt_tf32_kernel<<<(n4 + 255) / 256, 256>>>(x,  gx,  n4);
    cvt_tf32_kernel<<<(n4 + 255) / 256, 256>>>(Wq, wcq, n4);
    cvt_tf32_kernel<<<(n4 + 255) / 256, 256>>>(Wk, wck, n4);
    cvt_tf32_kernel<<<(n4 + 255) / 256, 256>>>(Wv, wcv, n4);
    cvt_tf32_kernel<<<(n4 + 255) / 256, 256>>>(Wo, wco, n4);

    // K1: QKV projections
    gemm_mma_kernel<<<dim3(HIDDEN / BN, MROWS / BM, 3), 256, GEMM_SMEM>>>(
        gx, wcq, wck, wcv, gq, gk, gv, nullptr, 1);

    // K2: RoPE + tf32 rounding of k, v
    int rope_n = BATCH * HEADS * SEQ * 64;
    rope_kernel<<<(rope_n + 255) / 256, 256>>>(gq, gk, gv);

    // K3: tensor-core flash attention
    dim3 gfl(SEQ / 64, BATCH * HEADS);
    flash_kernel<<<gfl, 256, FLASH_SMEM>>>(gq, gk, gv, pm, pol, mw, ga);

    // K4: output projection + bias
    gemm_mma_kernel<<<dim3(HIDDEN / BN, MROWS / BM, 1), 256, GEMM_SMEM>>>(
        ga, wco, wco, wco, out, out, out, bo, 0);
}

// round 5
// speedup vs baseline: 3.1669x; 1.0027x over previous
#include <cuda_runtime.h>
#include <math.h>
#include <stdint.h>

#define HIDDEN   2048
#define HEADS    16
#define HEAD_DIM 128
#define BATCH    2
#define SEQ      1024
#define MROWS    (BATCH*SEQ)

// ---------------- scratch (allocation-free: device globals) ----------------
__device__ float g_q[BATCH*HEADS*SEQ*HEAD_DIM];
__device__ float g_k[BATCH*HEADS*SEQ*HEAD_DIM];
__device__ float g_v[BATCH*HEADS*SEQ*HEAD_DIM];
__device__ float g_attn[MROWS*HIDDEN];
__device__ float g_xc[MROWS*HIDDEN];        // tf32-rounded x
__device__ float g_wc[4*HIDDEN*HIDDEN];     // tf32-rounded weights, original [K,N] layout

// ============================================================================
// helpers
// ============================================================================
__device__ __forceinline__ uint32_t smem_u32(const void* p) {
    uint32_t a;
    asm("{ .reg .u64 t; cvta.to.shared.u64 t, %1; cvt.u32.u64 %0, t; }"
        : "=r"(a) : "l"(p));
    return a;
}
__device__ __forceinline__ float to_tf32(float x) {
    uint32_t u;
    asm("cvt.rna.tf32.f32 %0, %1;" : "=r"(u) : "f"(x));
    return __uint_as_float(u);
}
__device__ __forceinline__ void cpa16(uint32_t s, const void* g) {
    asm volatile("cp.async.cg.shared.global [%0], [%1], 16;" :: "r"(s), "l"(g));
}
#define CPA_COMMIT() asm volatile("cp.async.commit_group;" ::: "memory")
template<int N> __device__ __forceinline__ void cpa_wait() {
    asm volatile("cp.async.wait_group %0;" :: "n"(N) : "memory");
}
__device__ __forceinline__ void mma16n8k8(float* c, const uint32_t* a, const uint32_t* b) {
    asm volatile(
        "mma.sync.aligned.m16n8k8.row.col.f32.tf32.tf32.f32 "
        "{%0,%1,%2,%3}, {%4,%5,%6,%7}, {%8,%9}, {%0,%1,%2,%3};"
        : "+f"(c[0]), "+f"(c[1]), "+f"(c[2]), "+f"(c[3])
        : "r"(a[0]), "r"(a[1]), "r"(a[2]), "r"(a[3]), "r"(b[0]), "r"(b[1]));
}

// 2^x via FMA-pipe polynomial (no MUFU). |rel err| < ~2e-6 on valid range.
__device__ __forceinline__ float exp2c(float x) {
    x = fmaxf(x, -126.f);
    float fl = floorf(x);
    float f  = x - fl;
    int   i  = (int)fl;
    float r = 1.52527338e-5f;
    r = fmaf(r, f, 1.54035304e-4f);
    r = fmaf(r, f, 1.33335581e-3f);
    r = fmaf(r, f, 9.61812911e-3f);
    r = fmaf(r, f, 5.55041087e-2f);
    r = fmaf(r, f, 2.40226507e-1f);
    r = fmaf(r, f, 6.93147181e-1f);
    r = fmaf(r, f, 1.0f);
    return r * __int_as_float((i + 127) << 23);
}
// log2(1+u) for u in [0, ~0.101] via deg-7 series, abs err < 2e-9
__device__ __forceinline__ float log2p_small(float u) {
    float r = 0.14285714f;
    r = fmaf(r, u, -0.16666667f);
    r = fmaf(r, u, 0.2f);
    r = fmaf(r, u, -0.25f);
    r = fmaf(r, u, 0.33333333f);
    r = fmaf(r, u, -0.5f);
    r = fmaf(r, u, 1.0f);
    return r * u * 1.4426950408889634f;
}

// ============================================================================
// K0: elementwise tf32 rounding, 5 tensors in one launch (z-grid)
// ============================================================================
__global__ void cvt_tf32_kernel5(
    const float* __restrict__ s0, const float* __restrict__ s1,
    const float* __restrict__ s2, const float* __restrict__ s3,
    const float* __restrict__ s4,
    float* __restrict__ d0, float* __restrict__ d1,
    float* __restrict__ d2, float* __restrict__ d3,
    float* __restrict__ d4, int n4)
{
    int z = blockIdx.z;
    const float* src = (z == 0) ? s0 : (z == 1) ? s1 : (z == 2) ? s2 : (z == 3) ? s3 : s4;
    float* dst       = (z == 0) ? d0 : (z == 1) ? d1 : (z == 2) ? d2 : (z == 3) ? d3 : d4;
    int i = blockIdx.x * blockDim.x + threadIdx.x;
    if (i >= n4) return;
    float4 v = ((const float4*)src)[i];
    v.x = to_tf32(v.x); v.y = to_tf32(v.y); v.z = to_tf32(v.z); v.w = to_tf32(v.w);
    ((float4*)dst)[i] = v;
}

// ============================================================================
// K1/K4: tf32 mma.sync GEMM. C = A[2048x2048] * W[K,N] (+bias)
// CTA 128x128, BK=32, 8 warps (warp tile 64x32), cp.async 3-stage,
// single __syncthreads per k-tile.
// ============================================================================
#define BM 128
#define BN 128
#define BK 32
#define PADK 36
#define PADN 136
#define ASTAGE (BM*PADK)
#define BSTAGE (BK*PADN)
#define NKT (HIDDEN / BK)
#define STAGE_FLOATS (ASTAGE + BSTAGE)
#define NSTAGE 3
#define GEMM_SMEM (NSTAGE * STAGE_FLOATS * 4)

__global__ __launch_bounds__(256, 2) void gemm_mma_kernel(
    const float* __restrict__ A,
    const float* __restrict__ B0, const float* __restrict__ B1, const float* __restrict__ B2,
    float* __restrict__ D0, float* __restrict__ D1, float* __restrict__ D2,
    const float* __restrict__ bias, int mode)
{
    extern __shared__ float sm[];
    const int t    = threadIdx.x;
    const int wid  = t >> 5;
    const int lane = t & 31;
    const int gid  = lane >> 2;
    const int tig  = lane & 3;
    const int z = blockIdx.z;
    const float* __restrict__ B = (z == 0) ? B0 : (z == 1) ? B1 : B2;
    float* __restrict__ D       = (z == 0) ? D0 : (z == 1) ? D1 : D2;
    const int n0 = blockIdx.x * BN;
    const int m0 = blockIdx.y * BM;
    const int wm = (wid & 1) * 64;
    const int wn = (wid >> 1) * 32;

    const uint32_t smb = smem_u32(sm);

    // A cp.async mapping (rows m, k-contig)
    const int ldr = t >> 3;
    const int ldc = (t & 7) * 4;
    const float* agp = A + (size_t)(m0 + ldr) * HIDDEN + ldc;
    const uint32_t asb = smb + (uint32_t)(ldr * PADK + ldc) * 4;
    // B cp.async mapping (rows k, n-contig)
    const int br = t >> 5;
    const int bc = (t & 31) * 4;
    const float* bgp = B + (size_t)br * HIDDEN + n0 + bc;
    const uint32_t bsb = smb + (uint32_t)(ASTAGE + br * PADN + bc) * 4;

    float acc[4][4][4];
#pragma unroll
    for (int mi = 0; mi < 4; ++mi)
#pragma unroll
        for (int ni = 0; ni < 4; ++ni)
#pragma unroll
            for (int j = 0; j < 4; ++j) acc[mi][ni][j] = 0.f;

    auto issue = [&](int kt, int s) {
        const uint32_t so = (uint32_t)(s * STAGE_FLOATS) * 4;
        const int ko = kt * BK;
#pragma unroll
        for (int i = 0; i < 4; ++i)
            cpa16(asb + so + (uint32_t)(i * 32 * PADK) * 4, agp + (size_t)i * 32 * HIDDEN + ko);
#pragma unroll
        for (int i = 0; i < 4; ++i)
            cpa16(bsb + so + (uint32_t)(i * 8 * PADN) * 4, bgp + (size_t)(i * 8 + ko) * HIDDEN);
        CPA_COMMIT();
    };

    issue(0, 0);
    issue(1, 1);

    int cs = 0;   // compute stage
    int is = 2;   // next issue stage

    for (int kt = 0; kt < NKT; ++kt) {
        cpa_wait<1>();       // group kt complete (in-order), kt+1 may pend
        __syncthreads();     // data visible; prev stage fully consumed by all warps

        if (kt + 2 < NKT) issue(kt + 2, is);
        else              CPA_COMMIT();        // empty group keeps count aligned
        is = (is == 2) ? 0 : is + 1;

        const uint32_t* Asu = (const uint32_t*)(sm + cs * STAGE_FLOATS);
        const uint32_t* Bsu = Asu + ASTAGE;
        cs = (cs == 2) ? 0 : cs + 1;

#pragma unroll
        for (int ks = 0; ks < 4; ++ks) {
            const int k0 = ks * 8;
            uint32_t a[4][4], b[4][2];
#pragma unroll
            for (int mi = 0; mi < 4; ++mi) {
                const int r = wm + mi * 16 + gid;
                a[mi][0] = Asu[r * PADK + k0 + tig];
                a[mi][1] = Asu[(r + 8) * PADK + k0 + tig];
                a[mi][2] = Asu[r * PADK + k0 + tig + 4];
                a[mi][3] = Asu[(r + 8) * PADK + k0 + tig + 4];
            }
#pragma unroll
            for (int ni = 0; ni < 4; ++ni) {
                const int c = wn + ni * 8 + gid;
                b[ni][0] = Bsu[(k0 + tig) * PADN + c];
                b[ni][1] = Bsu[(k0 + tig + 4) * PADN + c];
            }
#pragma unroll
            for (int mi = 0; mi < 4; ++mi)
#pragma unroll
                for (int ni = 0; ni < 4; ++ni)
                    mma16n8k8(acc[mi][ni], a[mi], b[ni]);
        }
    }

#pragma unroll
    for (int mi = 0; mi < 4; ++mi) {
#pragma unroll
        for (int ni = 0; ni < 4; ++ni) {
            const int c = wn + ni * 8 + 2 * tig;
            const int r0 = wm + mi * 16 + gid;
            const int r1 = r0 + 8;
            float2 v0 = {acc[mi][ni][0], acc[mi][ni][1]};
            float2 v1 = {acc[mi][ni][2], acc[mi][ni][3]};
            if (mode == 0) {
                float2 bb = *(const float2*)&bias[n0 + c];
                v0.x += bb.x; v0.y += bb.y;
                v1.x += bb.x; v1.y += bb.y;
                *(float2*)&D[(size_t)(m0 + r0) * HIDDEN + n0 + c] = v0;
                *(float2*)&D[(size_t)(m0 + r1) * HIDDEN + n0 + c] = v1;
            } else {
                const int h = blockIdx.x;
                int m = m0 + r0;
                int bb0 = m >> 10, s0q = m & 1023;
                *(float2*)&D[(((size_t)(bb0 * HEADS + h) * SEQ + s0q) << 7) + c] = v0;
                m = m0 + r1;
                int bb1 = m >> 10, s1q = m & 1023;
                *(float2*)&D[(((size_t)(bb1 * HEADS + h) * SEQ + s1q) << 7) + c] = v1;
            }
        }
    }
}

// ============================================================================
// K2: RoPE in place on q,k; k,v rounded to tf32 (flash MMA operands)
// ============================================================================
__global__ void rope_kernel(float* __restrict__ q, float* __restrict__ k, float* __restrict__ v)
{
    int idx = blockIdx.x * blockDim.x + threadIdx.x;
    if (idx >= BATCH * HEADS * SEQ * 64) return;
    int i  = idx & 63;
    int s  = (idx >> 6) & (SEQ - 1);
    int bh = idx >> 16;

    float inv = expf(-(float)(2 * i) * (9.210340371976184f / 128.f));
    float th  = (float)s * inv;
    float sn, cs;
    sincosf(th, &sn, &cs);

    size_t base = ((size_t)bh * SEQ + s) * HEAD_DIM + i;
    float q1 = q[base], q2 = q[base + 64];
    q[base]      = q1 * cs - q2 * sn;        // full fp32 (split in flash)
    q[base + 64] = q2 * cs + q1 * sn;
    float k1 = k[base], k2 = k[base + 64];
    k[base]      = to_tf32(k1 * cs - k2 * sn);
    k[base + 64] = to_tf32(k2 * cs + k1 * sn);
    v[base]      = to_tf32(v[base]);
    v[base + 64] = to_tf32(v[base + 64]);
}

// ============================================================================
// K3: causal flash attention, tf32 mma.sync, fused bias, log2-domain softmax.
// CTA: 64 q-rows, 8 warps (4m x 2n). K/V double-buffered cp.async.
// Q split hi/lo (error-free Q side). grid = (16, 32).
// ============================================================================
#define FPADD 132
#define FPADV 136
#define FPADP 68
#define OQH  0
#define OQL  8448
#define OKS  16896
#define OVS  33792
#define OPS  51200
#define ORM  55552
#define ORL  55616
#define ORDM 55680
#define ORDS 55808
#define FLASH_FLOATS 55936
#define FLASH_SMEM (FLASH_FLOATS * 4)

__global__ __launch_bounds__(256, 1) void flash_kernel(
    const float* __restrict__ q, const float* __restrict__ k, const float* __restrict__ v,
    const float* __restrict__ pm, const float* __restrict__ pol, const float* __restrict__ mw,
    float* __restrict__ attn)
{
    extern __shared__ float smf[];
    const uint32_t smb = smem_u32(smf);

    const int t    = threadIdx.x;
    const int wid  = t >> 5;
    const int lane = t & 31;
    const int gid  = lane >> 2;
    const int tig  = lane & 3;
    const int wm   = (wid & 3) * 16;
    const int wni  = wid >> 2;
    const int wn   = wni * 32;
    const int wd   = wni * 64;

    const int qt = (gridDim.x - 1) - blockIdx.x;
    const int bh = blockIdx.y;
    const int q0 = qt * 64;

    const float* qb = q + (size_t)bh * SEQ * HEAD_DIM;
    const float* kb = k + (size_t)bh * SEQ * HEAD_DIM;
    const float* vb = v + (size_t)bh * SEQ * HEAD_DIM;
    const size_t moff = (size_t)bh * SEQ * SEQ;

    for (int idx = t; idx < 64 * 32; idx += 256) {
        int r  = idx >> 5;
        int c4 = (idx & 31) * 4;
        float4 x = *(const float4*)&qb[(size_t)(q0 + r) * HEAD_DIM + c4];
        float* qh = smf + OQH + r * FPADD + c4;
        float* ql = smf + OQL + r * FPADD + c4;
        float h0 = to_tf32(x.x); qh[0] = h0; ql[0] = to_tf32(x.x - h0);
        float h1 = to_tf32(x.y); qh[1] = h1; ql[1] = to_tf32(x.y - h1);
        float h2 = to_tf32(x.z); qh[2] = h2; ql[2] = to_tf32(x.z - h2);
        float h3 = to_tf32(x.w); qh[3] = h3; ql[3] = to_tf32(x.w - h3);
    }
    if (t < 64) { smf[ORM + t] = -1e30f; smf[ORL + t] = 0.f; }

    auto issueKV = [&](int jt, int s) {
        const int j0 = jt * 64;
#pragma unroll
        for (int i = 0; i < 8; ++i) {
            int idx = i * 256 + t;
            int r  = idx >> 5;
            int c4 = (idx & 31) * 4;
            const float* kg = &kb[(size_t)(j0 + r) * HEAD_DIM + c4];
            const float* vg = &vb[(size_t)(j0 + r) * HEAD_DIM + c4];
            cpa16(smb + (uint32_t)(OKS + s * 8448 + r * FPADD + c4) * 4, kg);
            cpa16(smb + (uint32_t)(OVS + s * 8704 + r * FPADV + c4) * 4, vg);
        }
        CPA_COMMIT();
    };

    issueKV(0, 0);

    const float SC2  = 0.08838834764831845f * 1.4426950408889634f;
    const float CPM  = 0.05f * 1.4426950408889634f;
    const float CPO  = 0.1f  * 1.4426950408889634f;

    const int row0  = wm + gid;
    const int row1  = row0 + 8;
    const int grow0 = q0 + row0;
    const int grow1 = q0 + row1;

    float acc_o[8][4];
#pragma unroll
    for (int ni = 0; ni < 8; ++ni)
#pragma unroll
        for (int j = 0; j < 4; ++j) acc_o[ni][j] = 0.f;

    for (int jt = 0; jt <= qt; ++jt) {
        if (jt < qt) { issueKV(jt + 1, (jt + 1) & 1); cpa_wait<1>(); }
        else         { cpa_wait<0>(); }
        __syncthreads();

        const float* Kb = smf + OKS + (jt & 1) * 8448;
        const float* Vb = smf + OVS + (jt & 1) * 8704;
        const int j0c = jt * 64;

        float accs[4][4];
#pragma unroll
        for (int ni = 0; ni < 4; ++ni)
#pragma unroll
            for (int j = 0; j < 4; ++j) accs[ni][j] = 0.f;

#pragma unroll
        for (int ks = 0; ks < 16; ++ks) {
            const int k0 = ks * 8;
            uint32_t ah[4], al[4], b[4][2];
            const uint32_t* Qh = (const uint32_t*)(smf + OQH);
            const uint32_t* Ql = (const uint32_t*)(smf + OQL);
            ah[0] = Qh[row0 * FPADD + k0 + tig];
            ah[1] = Qh[row1 * FPADD + k0 + tig];
            ah[2] = Qh[row0 * FPADD + k0 + tig + 4];
            ah[3] = Qh[row1 * FPADD + k0 + tig + 4];
            al[0] = Ql[row0 * FPADD + k0 + tig];
            al[1] = Ql[row1 * FPADD + k0 + tig];
            al[2] = Ql[row0 * FPADD + k0 + tig + 4];
            al[3] = Ql[row1 * FPADD + k0 + tig + 4];
            const uint32_t* Ku = (const uint32_t*)Kb;
#pragma unroll
            for (int ni = 0; ni < 4; ++ni) {
                const int c = wn + ni * 8 + gid;
                b[ni][0] = Ku[c * FPADD + k0 + tig];
                b[ni][1] = Ku[c * FPADD + k0 + tig + 4];
            }
#pragma unroll
            for (int ni = 0; ni < 4; ++ni) {
                mma16n8k8(accs[ni], ah, b[ni]);
                mma16n8k8(accs[ni], al, b[ni]);
            }
        }

        const bool diag = (jt == qt);
        float ml0 = -1e30f, ml1 = -1e30f;
        const size_t mr0 = moff + (size_t)grow0 * SEQ + j0c;
        const size_t mr1 = moff + (size_t)grow1 * SEQ + j0c;
#pragma unroll
        for (int ni = 0; ni < 4; ++ni) {
            const int cl = wn + ni * 8 + 2 * tig;
            float2 a0 = *(const float2*)&pm[mr0 + cl];
            float2 b0 = *(const float2*)&pol[mr0 + cl];
            float2 c0 = *(const float2*)&mw[mr0 + cl];
            float2 a1 = *(const float2*)&pm[mr1 + cl];
            float2 b1 = *(const float2*)&pol[mr1 + cl];
            float2 c1 = *(const float2*)&mw[mr1 + cl];
            float s0 = fmaf(accs[ni][0], SC2, fmaf(a0.x, CPM, fmaf(b0.x, CPO, log2p_small(fmaf(c0.x, 0.1f, 1e-8f)))));
            float s1 = fmaf(accs[ni][1], SC2, fmaf(a0.y, CPM, fmaf(b0.y, CPO, log2p_small(fmaf(c0.y, 0.1f, 1e-8f)))));
            float s2 = fmaf(accs[ni][2], SC2, fmaf(a1.x, CPM, fmaf(b1.x, CPO, log2p_small(fmaf(c1.x, 0.1f, 1e-8f)))));
            float s3 = fmaf(accs[ni][3], SC2, fmaf(a1.y, CPM, fmaf(b1.y, CPO, log2p_small(fmaf(c1.y, 0.1f, 1e-8f)))));
            if (diag) {
                if (cl     > row0) s0 = -1e30f;
                if (cl + 1 > row0) s1 = -1e30f;
                if (cl     > row1) s2 = -1e30f;
                if (cl + 1 > row1) s3 = -1e30f;
            }
            accs[ni][0] = s0; accs[ni][1] = s1; accs[ni][2] = s2; accs[ni][3] = s3;
            ml0 = fmaxf(ml0, fmaxf(s0, s1));
            ml1 = fmaxf(ml1, fmaxf(s2, s3));
        }
#pragma unroll
        for (int o = 1; o < 4; o <<= 1) {
            ml0 = fmaxf(ml0, __shfl_xor_sync(0xffffffffu, ml0, o));
            ml1 = fmaxf(ml1, __shfl_xor_sync(0xffffffffu, ml1, o));
        }
        if (tig == 0) {
            smf[ORDM + wni * 64 + row0] = ml0;
            smf[ORDM + wni * 64 + row1] = ml1;
        }
        float mold0 = smf[ORM + row0];
        float mold1 = smf[ORM + row1];
        __syncthreads();

        float mn0 = fmaxf(mold0, fmaxf(smf[ORDM + row0], smf[ORDM + 64 + row0]));
        float mn1 = fmaxf(mold1, fmaxf(smf[ORDM + row1], smf[ORDM + 64 + row1]));
        float al0 = exp2c(mold0 - mn0);
        float al1 = exp2c(mold1 - mn1);

        float sum0 = 0.f, sum1 = 0.f;
#pragma unroll
        for (int ni = 0; ni < 4; ++ni) {
            const int cl = wn + ni * 8 + 2 * tig;
            float p0 = exp2c(accs[ni][0] - mn0);
            float p1 = exp2c(accs[ni][1] - mn0);
            float p2 = exp2c(accs[ni][2] - mn1);
            float p3 = exp2c(accs[ni][3] - mn1);
            sum0 += p0 + p1;
            sum1 += p2 + p3;
            smf[OPS + row0 * FPADP + cl]     = to_tf32(p0);
            smf[OPS + row0 * FPADP + cl + 1] = to_tf32(p1);
            smf[OPS + row1 * FPADP + cl]     = to_tf32(p2);
            smf[OPS + row1 * FPADP + cl + 1] = to_tf32(p3);
        }
#pragma unroll
        for (int o = 1; o < 4; o <<= 1) {
            sum0 += __shfl_xor_sync(0xffffffffu, sum0, o);
            sum1 += __shfl_xor_sync(0xffffffffu, sum1, o);
        }
        if (tig == 0) {
            smf[ORDS + wni * 64 + row0] = sum0;
            smf[ORDS + wni * 64 + row1] = sum1;
        }
#pragma unroll
        for (int ni = 0; ni < 8; ++ni) {
            acc_o[ni][0] *= al0; acc_o[ni][1] *= al0;
            acc_o[ni][2] *= al1; acc_o[ni][3] *= al1;
        }
        __syncthreads();

        if (t < 64) {
            float mo = smf[ORM + t];
            float mn = fmaxf(mo, fmaxf(smf[ORDM + t], smf[ORDM + 64 + t]));
            float a  = exp2c(mo - mn);
            smf[ORL + t] = smf[ORL + t] * a + smf[ORDS + t] + smf[ORDS + 64 + t];
            smf[ORM + t] = mn;
        }

        const uint32_t* Pu = (const uint32_t*)(smf + OPS);
        const uint32_t* Vu = (const uint32_t*)Vb;
#pragma unroll
        for (int ks = 0; ks < 8; ++ks) {
            const int k0 = ks * 8;
            uint32_t a[4], b[8][2];
            a[0] = Pu[row0 * FPADP + k0 + tig];
            a[1] = Pu[row1 * FPADP + k0 + tig];
            a[2] = Pu[row0 * FPADP + k0 + tig + 4];
            a[3] = Pu[row1 * FPADP + k0 + tig + 4];
#pragma unroll
            for (int ni = 0; ni < 8; ++ni) {
                const int c = wd + ni * 8 + gid;
                b[ni][0] = Vu[(k0 + tig) * FPADV + c];
                b[ni][1] = Vu[(k0 + tig + 4) * FPADV + c];
            }
#pragma unroll
            for (int ni = 0; ni < 8; ++ni)
                mma16n8k8(acc_o[ni], a, b[ni]);
        }
    }

    __syncthreads();
    const float l0 = 1.f / smf[ORL + row0];
    const float l1 = 1.f / smf[ORL + row1];
    const int bb = bh >> 4;
    const int h  = bh & 15;
    float* o0 = attn + ((size_t)(bb * SEQ + grow0)) * HIDDEN + h * HEAD_DIM;
    float* o1 = attn + ((size_t)(bb * SEQ + grow1)) * HIDDEN + h * HEAD_DIM;
#pragma unroll
    for (int ni = 0; ni < 8; ++ni) {
        const int d = wd + ni * 8 + 2 * tig;
        float2 w0 = {to_tf32(acc_o[ni][0] * l0), to_tf32(acc_o[ni][1] * l0)};
        float2 w1 = {to_tf32(acc_o[ni][2] * l1), to_tf32(acc_o[ni][3] * l1)};
        *(float2*)(o0 + d) = w0;
        *(float2*)(o1 + d) = w1;
    }
}

// ============================================================================
// host launcher
// ============================================================================
extern "C" void kernel_launch(void* const* d_in, const int* in_sizes, int n_in,
                              void* d_out, int out_size)
{
    const float* x   = (const float*)d_in[0];
    const float* pm  = (const float*)d_in[1];
    const float* pol = (const float*)d_in[2];
    const float* mw  = (const float*)d_in[3];
    const float* Wq  = (const float*)d_in[4];
    const float* Wk  = (const float*)d_in[5];
    const float* Wv  = (const float*)d_in[6];
    const float* Wo  = (const float*)d_in[7];
    const float* bo  = (const float*)d_in[8];
    float* out = (float*)d_out;

    float *gq, *gk, *gv, *ga, *gw, *gx;
    cudaGetSymbolAddress((void**)&gq, g_q);
    cudaGetSymbolAddress((void**)&gk, g_k);
    cudaGetSymbolAddress((void**)&gv, g_v);
    cudaGetSymbolAddress((void**)&ga, g_attn);
    cudaGetSymbolAddress((void**)&gw, g_wc);
    cudaGetSymbolAddress((void**)&gx, g_xc);

    cudaFuncSetAttribute(flash_kernel,
                         cudaFuncAttributeMaxDynamicSharedMemorySize, FLASH_SMEM);
    cudaFuncSetAttribute(gemm_mma_kernel,
                         cudaFuncAttributeMaxDynamicSharedMemorySize, GEMM_SMEM);

    float* wcq = gw;
    float* wck = gw + (size_t)HIDDEN * HIDDEN;
    float* wcv = gw + 2 * (size_t)HIDDEN * HIDDEN;
    float* wco = gw + 3 * (size_t)HIDDEN * HIDDEN;

    const int n4 = HIDDEN * HIDDEN / 4;
    cvt_tf32_kernel5<<<dim3((n4 + 255) / 256, 1, 5), 256>>>(
        x, Wq, Wk, Wv, Wo, gx, wcq, wck, wcv, wco, n4);

    // K1: QKV projections
    gemm_mma_kernel<<<dim3(HIDDEN / BN, MROWS / BM, 3), 256, GEMM_SMEM>>>(
        gx, wcq, wck, wcv, gq, gk, gv, nullptr, 1);

    // K2: RoPE + tf32 rounding of k, v
    int rope_n = BATCH * HEADS * SEQ * 64;
    rope_kernel<<<(rope_n + 255) / 256, 256>>>(gq, gk, gv);

    // K3: tensor-core flash attention
    dim3 gfl(SEQ / 64, BATCH * HEADS);
    flash_kernel<<<gfl, 256, FLASH_SMEM>>>(gq, gk, gv, pm, pol, mw, ga);

    // K4: output projection + bias
    gemm_mma_kernel<<<dim3(HIDDEN / BN, MROWS / BM, 1), 256, GEMM_SMEM>>>(
        ga, wco, wco, wco, out, out, out, bo, 0);
}

// round 6
// speedup vs baseline: 3.1755x; 1.0027x over previous
#include <cuda_runtime.h>
#include <math.h>
#include <stdint.h>

#define HIDDEN   2048
#define HEADS    16
#define HEAD_DIM 128
#define BATCH    2
#define SEQ      1024
#define MROWS    (BATCH*SEQ)

// ---------------- scratch (allocation-free: device globals) ----------------
__device__ float g_q[BATCH*HEADS*SEQ*HEAD_DIM];
__device__ float g_k[BATCH*HEADS*SEQ*HEAD_DIM];
__device__ float g_v[BATCH*HEADS*SEQ*HEAD_DIM];
__device__ float g_attn[MROWS*HIDDEN];
__device__ float g_xc[MROWS*HIDDEN];        // tf32-rounded x
__device__ float g_wc[4*HIDDEN*HIDDEN];     // tf32-rounded weights, original [K,N] layout

// ============================================================================
// helpers
// ============================================================================
__device__ __forceinline__ uint32_t smem_u32(const void* p) {
    uint32_t a;
    asm("{ .reg .u64 t; cvta.to.shared.u64 t, %1; cvt.u32.u64 %0, t; }"
        : "=r"(a) : "l"(p));
    return a;
}
__device__ __forceinline__ float to_tf32(float x) {
    uint32_t u;
    asm("cvt.rna.tf32.f32 %0, %1;" : "=r"(u) : "f"(x));
    return __uint_as_float(u);
}
__device__ __forceinline__ void cpa16(uint32_t s, const void* g) {
    asm volatile("cp.async.cg.shared.global [%0], [%1], 16;" :: "r"(s), "l"(g));
}
#define CPA_COMMIT() asm volatile("cp.async.commit_group;" ::: "memory")
template<int N> __device__ __forceinline__ void cpa_wait() {
    asm volatile("cp.async.wait_group %0;" :: "n"(N) : "memory");
}
__device__ __forceinline__ void mma16n8k8(float* c, const uint32_t* a, const uint32_t* b) {
    asm volatile(
        "mma.sync.aligned.m16n8k8.row.col.f32.tf32.tf32.f32 "
        "{%0,%1,%2,%3}, {%4,%5,%6,%7}, {%8,%9}, {%0,%1,%2,%3};"
        : "+f"(c[0]), "+f"(c[1]), "+f"(c[2]), "+f"(c[3])
        : "r"(a[0]), "r"(a[1]), "r"(a[2]), "r"(a[3]), "r"(b[0]), "r"(b[1]));
}

// 2^x via FMA-pipe polynomial (no MUFU). |rel err| < ~2e-6 on valid range.
__device__ __forceinline__ float exp2c(float x) {
    x = fmaxf(x, -126.f);
    float fl = floorf(x);
    float f  = x - fl;
    int   i  = (int)fl;
    float r = 1.52527338e-5f;
    r = fmaf(r, f, 1.54035304e-4f);
    r = fmaf(r, f, 1.33335581e-3f);
    r = fmaf(r, f, 9.61812911e-3f);
    r = fmaf(r, f, 5.55041087e-2f);
    r = fmaf(r, f, 2.40226507e-1f);
    r = fmaf(r, f, 6.93147181e-1f);
    r = fmaf(r, f, 1.0f);
    return r * __int_as_float((i + 127) << 23);
}
// log2(1+u) for u in [0, ~0.101] via deg-7 series, abs err < 2e-9
__device__ __forceinline__ float log2p_small(float u) {
    float r = 0.14285714f;
    r = fmaf(r, u, -0.16666667f);
    r = fmaf(r, u, 0.2f);
    r = fmaf(r, u, -0.25f);
    r = fmaf(r, u, 0.33333333f);
    r = fmaf(r, u, -0.5f);
    r = fmaf(r, u, 1.0f);
    return r * u * 1.4426950408889634f;
}

// ============================================================================
// K0: elementwise tf32 rounding, 5 tensors in one launch (z-grid)
// ============================================================================
__global__ void cvt_tf32_kernel5(
    const float* __restrict__ s0, const float* __restrict__ s1,
    const float* __restrict__ s2, const float* __restrict__ s3,
    const float* __restrict__ s4,
    float* __restrict__ d0, float* __restrict__ d1,
    float* __restrict__ d2, float* __restrict__ d3,
    float* __restrict__ d4, int n4)
{
    int z = blockIdx.z;
    const float* src = (z == 0) ? s0 : (z == 1) ? s1 : (z == 2) ? s2 : (z == 3) ? s3 : s4;
    float* dst       = (z == 0) ? d0 : (z == 1) ? d1 : (z == 2) ? d2 : (z == 3) ? d3 : d4;
    int i = blockIdx.x * blockDim.x + threadIdx.x;
    if (i >= n4) return;
    float4 v = ((const float4*)src)[i];
    v.x = to_tf32(v.x); v.y = to_tf32(v.y); v.z = to_tf32(v.z); v.w = to_tf32(v.w);
    ((float4*)dst)[i] = v;
}

// ============================================================================
// K1/K4: tf32 mma.sync GEMM. C = A[2048x2048] * W[K,N] (+bias)
// CTA 128x128, BK=32, 8 warps (warp tile 64x32), cp.async 3-stage.
// ============================================================================
#define BM 128
#define BN 128
#define BK 32
#define PADK 36
#define PADN 136
#define ASTAGE (BM*PADK)
#define BSTAGE (BK*PADN)
#define NKT (HIDDEN / BK)
#define STAGE_FLOATS (ASTAGE + BSTAGE)
#define NSTAGE 3
#define GEMM_SMEM (NSTAGE * STAGE_FLOATS * 4)

__global__ __launch_bounds__(256, 2) void gemm_mma_kernel(
    const float* __restrict__ A,
    const float* __restrict__ B0, const float* __restrict__ B1, const float* __restrict__ B2,
    float* __restrict__ D0, float* __restrict__ D1, float* __restrict__ D2,
    const float* __restrict__ bias, int mode)
{
    extern __shared__ float sm[];
    const int t    = threadIdx.x;
    const int wid  = t >> 5;
    const int lane = t & 31;
    const int gid  = lane >> 2;
    const int tig  = lane & 3;
    const int z = blockIdx.z;
    const float* __restrict__ B = (z == 0) ? B0 : (z == 1) ? B1 : B2;
    float* __restrict__ D       = (z == 0) ? D0 : (z == 1) ? D1 : D2;
    const int n0 = blockIdx.x * BN;
    const int m0 = blockIdx.y * BM;
    const int wm = (wid & 1) * 64;
    const int wn = (wid >> 1) * 32;

    const uint32_t smb = smem_u32(sm);

    const int ldr = t >> 3;
    const int ldc = (t & 7) * 4;
    const float* agp = A + (size_t)(m0 + ldr) * HIDDEN + ldc;
    const uint32_t asb = smb + (uint32_t)(ldr * PADK + ldc) * 4;
    const int br = t >> 5;
    const int bc = (t & 31) * 4;
    const float* bgp = B + (size_t)br * HIDDEN + n0 + bc;
    const uint32_t bsb = smb + (uint32_t)(ASTAGE + br * PADN + bc) * 4;

    float acc[4][4][4];
#pragma unroll
    for (int mi = 0; mi < 4; ++mi)
#pragma unroll
        for (int ni = 0; ni < 4; ++ni)
#pragma unroll
            for (int j = 0; j < 4; ++j) acc[mi][ni][j] = 0.f;

    auto issue = [&](int kt, int s) {
        const uint32_t so = (uint32_t)(s * STAGE_FLOATS) * 4;
        const int ko = kt * BK;
#pragma unroll
        for (int i = 0; i < 4; ++i)
            cpa16(asb + so + (uint32_t)(i * 32 * PADK) * 4, agp + (size_t)i * 32 * HIDDEN + ko);
#pragma unroll
        for (int i = 0; i < 4; ++i)
            cpa16(bsb + so + (uint32_t)(i * 8 * PADN) * 4, bgp + (size_t)(i * 8 + ko) * HIDDEN);
        CPA_COMMIT();
    };

    issue(0, 0);
    issue(1, 1);

    int cs = 0;
    int is = 2;

    for (int kt = 0; kt < NKT; ++kt) {
        cpa_wait<1>();
        __syncthreads();

        if (kt + 2 < NKT) issue(kt + 2, is);
        else              CPA_COMMIT();
        is = (is == 2) ? 0 : is + 1;

        const uint32_t* Asu = (const uint32_t*)(sm + cs * STAGE_FLOATS);
        const uint32_t* Bsu = Asu + ASTAGE;
        cs = (cs == 2) ? 0 : cs + 1;

#pragma unroll
        for (int ks = 0; ks < 4; ++ks) {
            const int k0 = ks * 8;
            uint32_t a[4][4], b[4][2];
#pragma unroll
            for (int mi = 0; mi < 4; ++mi) {
                const int r = wm + mi * 16 + gid;
                a[mi][0] = Asu[r * PADK + k0 + tig];
                a[mi][1] = Asu[(r + 8) * PADK + k0 + tig];
                a[mi][2] = Asu[r * PADK + k0 + tig + 4];
                a[mi][3] = Asu[(r + 8) * PADK + k0 + tig + 4];
            }
#pragma unroll
            for (int ni = 0; ni < 4; ++ni) {
                const int c = wn + ni * 8 + gid;
                b[ni][0] = Bsu[(k0 + tig) * PADN + c];
                b[ni][1] = Bsu[(k0 + tig + 4) * PADN + c];
            }
#pragma unroll
            for (int mi = 0; mi < 4; ++mi)
#pragma unroll
                for (int ni = 0; ni < 4; ++ni)
                    mma16n8k8(acc[mi][ni], a[mi], b[ni]);
        }
    }

#pragma unroll
    for (int mi = 0; mi < 4; ++mi) {
#pragma unroll
        for (int ni = 0; ni < 4; ++ni) {
            const int c = wn + ni * 8 + 2 * tig;
            const int r0 = wm + mi * 16 + gid;
            const int r1 = r0 + 8;
            float2 v0 = {acc[mi][ni][0], acc[mi][ni][1]};
            float2 v1 = {acc[mi][ni][2], acc[mi][ni][3]};
            if (mode == 0) {
                float2 bb = *(const float2*)&bias[n0 + c];
                v0.x += bb.x; v0.y += bb.y;
                v1.x += bb.x; v1.y += bb.y;
                *(float2*)&D[(size_t)(m0 + r0) * HIDDEN + n0 + c] = v0;
                *(float2*)&D[(size_t)(m0 + r1) * HIDDEN + n0 + c] = v1;
            } else {
                const int h = blockIdx.x;
                int m = m0 + r0;
                int bb0 = m >> 10, s0q = m & 1023;
                *(float2*)&D[(((size_t)(bb0 * HEADS + h) * SEQ + s0q) << 7) + c] = v0;
                m = m0 + r1;
                int bb1 = m >> 10, s1q = m & 1023;
                *(float2*)&D[(((size_t)(bb1 * HEADS + h) * SEQ + s1q) << 7) + c] = v1;
            }
        }
    }
}

// ============================================================================
// K2: RoPE in place on q,k; k,v rounded to tf32 (flash MMA operands)
// ============================================================================
__global__ void rope_kernel(float* __restrict__ q, float* __restrict__ k, float* __restrict__ v)
{
    int idx = blockIdx.x * blockDim.x + threadIdx.x;
    if (idx >= BATCH * HEADS * SEQ * 64) return;
    int i  = idx & 63;
    int s  = (idx >> 6) & (SEQ - 1);
    int bh = idx >> 16;

    float inv = expf(-(float)(2 * i) * (9.210340371976184f / 128.f));
    float th  = (float)s * inv;
    float sn, cs;
    sincosf(th, &sn, &cs);

    size_t base = ((size_t)bh * SEQ + s) * HEAD_DIM + i;
    float q1 = q[base], q2 = q[base + 64];
    q[base]      = q1 * cs - q2 * sn;
    q[base + 64] = q2 * cs + q1 * sn;
    float k1 = k[base], k2 = k[base + 64];
    k[base]      = to_tf32(k1 * cs - k2 * sn);
    k[base + 64] = to_tf32(k2 * cs + k1 * sn);
    v[base]      = to_tf32(v[base]);
    v[base + 64] = to_tf32(v[base + 64]);
}

// ============================================================================
// K3: causal flash attention, tf32 mma.sync, fused bias, log2-domain softmax.
// 512 threads, 16 warps: 4m x 4n. Each warp: 16 q-rows x 16 S-cols (QK),
// 16 q-rows x 32 dims (PV). Q split hi/lo in smem. KV double-buffered.
// ============================================================================
#define FPADD 132
#define FPADV 136
#define FPADP 68
#define OQH  0
#define OQL  8448
#define OKS  16896
#define OVS  33792
#define OPS  51200
#define ORM  55552
#define ORL  55616
#define ORDM 55680
#define ORDS 55936
#define FLASH_FLOATS 56192
#define FLASH_SMEM (FLASH_FLOATS * 4)

__global__ __launch_bounds__(512, 1) void flash_kernel(
    const float* __restrict__ q, const float* __restrict__ k, const float* __restrict__ v,
    const float* __restrict__ pm, const float* __restrict__ pol, const float* __restrict__ mw,
    float* __restrict__ attn)
{
    extern __shared__ float smf[];
    const uint32_t smb = smem_u32(smf);

    const int t    = threadIdx.x;
    const int wid  = t >> 5;
    const int lane = t & 31;
    const int gid  = lane >> 2;
    const int tig  = lane & 3;
    const int wm   = (wid & 3) * 16;     // warp q-row offset
    const int wni  = wid >> 2;           // 0..3 n-warp index
    const int wn   = wni * 16;           // QK col offset
    const int wd   = wni * 32;           // PV dim offset

    const int qt = (gridDim.x - 1) - blockIdx.x;
    const int bh = blockIdx.y;
    const int q0 = qt * 64;

    const float* qb = q + (size_t)bh * SEQ * HEAD_DIM;
    const float* kb = k + (size_t)bh * SEQ * HEAD_DIM;
    const float* vb = v + (size_t)bh * SEQ * HEAD_DIM;
    const size_t moff = (size_t)bh * SEQ * SEQ;

    // ---- load Q tile, split hi/lo tf32 ----
    for (int idx = t; idx < 64 * 32; idx += 512) {
        int r  = idx >> 5;
        int c4 = (idx & 31) * 4;
        float4 x = *(const float4*)&qb[(size_t)(q0 + r) * HEAD_DIM + c4];
        float* qh = smf + OQH + r * FPADD + c4;
        float* ql = smf + OQL + r * FPADD + c4;
        float h0 = to_tf32(x.x); qh[0] = h0; ql[0] = to_tf32(x.x - h0);
        float h1 = to_tf32(x.y); qh[1] = h1; ql[1] = to_tf32(x.y - h1);
        float h2 = to_tf32(x.z); qh[2] = h2; ql[2] = to_tf32(x.z - h2);
        float h3 = to_tf32(x.w); qh[3] = h3; ql[3] = to_tf32(x.w - h3);
    }
    if (t < 64) { smf[ORM + t] = -1e30f; smf[ORL + t] = 0.f; }

    auto issueKV = [&](int jt, int s) {
        const int j0 = jt * 64;
#pragma unroll
        for (int i = 0; i < 4; ++i) {
            int idx = i * 512 + t;
            int r  = idx >> 5;
            int c4 = (idx & 31) * 4;
            const float* kg = &kb[(size_t)(j0 + r) * HEAD_DIM + c4];
            const float* vg = &vb[(size_t)(j0 + r) * HEAD_DIM + c4];
            cpa16(smb + (uint32_t)(OKS + s * 8448 + r * FPADD + c4) * 4, kg);
            cpa16(smb + (uint32_t)(OVS + s * 8704 + r * FPADV + c4) * 4, vg);
        }
        CPA_COMMIT();
    };

    issueKV(0, 0);

    const float SC2  = 0.08838834764831845f * 1.4426950408889634f;
    const float CPM  = 0.05f * 1.4426950408889634f;
    const float CPO  = 0.1f  * 1.4426950408889634f;

    const int row0  = wm + gid;
    const int row1  = row0 + 8;
    const int grow0 = q0 + row0;
    const int grow1 = q0 + row1;

    float acc_o[4][4];
#pragma unroll
    for (int ni = 0; ni < 4; ++ni)
#pragma unroll
        for (int j = 0; j < 4; ++j) acc_o[ni][j] = 0.f;

    for (int jt = 0; jt <= qt; ++jt) {
        if (jt < qt) { issueKV(jt + 1, (jt + 1) & 1); cpa_wait<1>(); }
        else         { cpa_wait<0>(); }
        __syncthreads();   // #1: KV ready; prev Ps consumed; rowm updated

        const float* Kb = smf + OKS + (jt & 1) * 8448;
        const float* Vb = smf + OVS + (jt & 1) * 8704;
        const int j0c = jt * 64;

        // ---- prefetch mask tiles into registers (overlaps with QK mma) ----
        const size_t mr0 = moff + (size_t)grow0 * SEQ + j0c;
        const size_t mr1 = moff + (size_t)grow1 * SEQ + j0c;
        float2 pa0[2], pb0[2], pc0[2], pa1[2], pb1[2], pc1[2];
#pragma unroll
        for (int ni = 0; ni < 2; ++ni) {
            const int cl = wn + ni * 8 + 2 * tig;
            pa0[ni] = *(const float2*)&pm[mr0 + cl];
            pb0[ni] = *(const float2*)&pol[mr0 + cl];
            pc0[ni] = *(const float2*)&mw[mr0 + cl];
            pa1[ni] = *(const float2*)&pm[mr1 + cl];
            pb1[ni] = *(const float2*)&pol[mr1 + cl];
            pc1[ni] = *(const float2*)&mw[mr1 + cl];
        }

        // ---- QK^T (split-Q tf32 mma) ----
        float accs[2][4];
#pragma unroll
        for (int ni = 0; ni < 2; ++ni)
#pragma unroll
            for (int j = 0; j < 4; ++j) accs[ni][j] = 0.f;

#pragma unroll
        for (int ks = 0; ks < 16; ++ks) {
            const int k0 = ks * 8;
            uint32_t ah[4], al[4], b[2][2];
            const uint32_t* Qh = (const uint32_t*)(smf + OQH);
            const uint32_t* Ql = (const uint32_t*)(smf + OQL);
            ah[0] = Qh[row0 * FPADD + k0 + tig];
            ah[1] = Qh[row1 * FPADD + k0 + tig];
            ah[2] = Qh[row0 * FPADD + k0 + tig + 4];
            ah[3] = Qh[row1 * FPADD + k0 + tig + 4];
            al[0] = Ql[row0 * FPADD + k0 + tig];
            al[1] = Ql[row1 * FPADD + k0 + tig];
            al[2] = Ql[row0 * FPADD + k0 + tig + 4];
            al[3] = Ql[row1 * FPADD + k0 + tig + 4];
            const uint32_t* Ku = (const uint32_t*)Kb;
#pragma unroll
            for (int ni = 0; ni < 2; ++ni) {
                const int c = wn + ni * 8 + gid;
                b[ni][0] = Ku[c * FPADD + k0 + tig];
                b[ni][1] = Ku[c * FPADD + k0 + tig + 4];
            }
#pragma unroll
            for (int ni = 0; ni < 2; ++ni) {
                mma16n8k8(accs[ni], ah, b[ni]);
                mma16n8k8(accs[ni], al, b[ni]);
            }
        }

        // ---- bias + causal + row max (log2 domain) ----
        const bool diag = (jt == qt);
        float ml0 = -1e30f, ml1 = -1e30f;
#pragma unroll
        for (int ni = 0; ni < 2; ++ni) {
            const int cl = wn + ni * 8 + 2 * tig;
            float s0 = fmaf(accs[ni][0], SC2, fmaf(pa0[ni].x, CPM, fmaf(pb0[ni].x, CPO, log2p_small(fmaf(pc0[ni].x, 0.1f, 1e-8f)))));
            float s1 = fmaf(accs[ni][1], SC2, fmaf(pa0[ni].y, CPM, fmaf(pb0[ni].y, CPO, log2p_small(fmaf(pc0[ni].y, 0.1f, 1e-8f)))));
            float s2 = fmaf(accs[ni][2], SC2, fmaf(pa1[ni].x, CPM, fmaf(pb1[ni].x, CPO, log2p_small(fmaf(pc1[ni].x, 0.1f, 1e-8f)))));
            float s3 = fmaf(accs[ni][3], SC2, fmaf(pa1[ni].y, CPM, fmaf(pb1[ni].y, CPO, log2p_small(fmaf(pc1[ni].y, 0.1f, 1e-8f)))));
            if (diag) {
                if (cl     > row0) s0 = -1e30f;
                if (cl + 1 > row0) s1 = -1e30f;
                if (cl     > row1) s2 = -1e30f;
                if (cl + 1 > row1) s3 = -1e30f;
            }
            accs[ni][0] = s0; accs[ni][1] = s1; accs[ni][2] = s2; accs[ni][3] = s3;
            ml0 = fmaxf(ml0, fmaxf(s0, s1));
            ml1 = fmaxf(ml1, fmaxf(s2, s3));
        }
#pragma unroll
        for (int o = 1; o < 4; o <<= 1) {
            ml0 = fmaxf(ml0, __shfl_xor_sync(0xffffffffu, ml0, o));
            ml1 = fmaxf(ml1, __shfl_xor_sync(0xffffffffu, ml1, o));
        }
        if (tig == 0) {
            smf[ORDM + wni * 64 + row0] = ml0;
            smf[ORDM + wni * 64 + row1] = ml1;
        }
        float mold0 = smf[ORM + row0];
        float mold1 = smf[ORM + row1];
        __syncthreads();   // #2: redm ready

        float mn0 = fmaxf(fmaxf(mold0, fmaxf(smf[ORDM + row0], smf[ORDM + 64 + row0])),
                          fmaxf(smf[ORDM + 128 + row0], smf[ORDM + 192 + row0]));
        float mn1 = fmaxf(fmaxf(mold1, fmaxf(smf[ORDM + row1], smf[ORDM + 64 + row1])),
                          fmaxf(smf[ORDM + 128 + row1], smf[ORDM + 192 + row1]));
        float al0 = exp2c(mold0 - mn0);
        float al1 = exp2c(mold1 - mn1);

        float sum0 = 0.f, sum1 = 0.f;
#pragma unroll
        for (int ni = 0; ni < 2; ++ni) {
            const int cl = wn + ni * 8 + 2 * tig;
            float p0 = exp2c(accs[ni][0] - mn0);
            float p1 = exp2c(accs[ni][1] - mn0);
            float p2 = exp2c(accs[ni][2] - mn1);
            float p3 = exp2c(accs[ni][3] - mn1);
            sum0 += p0 + p1;
            sum1 += p2 + p3;
            smf[OPS + row0 * FPADP + cl]     = to_tf32(p0);
            smf[OPS + row0 * FPADP + cl + 1] = to_tf32(p1);
            smf[OPS + row1 * FPADP + cl]     = to_tf32(p2);
            smf[OPS + row1 * FPADP + cl + 1] = to_tf32(p3);
        }
#pragma unroll
        for (int o = 1; o < 4; o <<= 1) {
            sum0 += __shfl_xor_sync(0xffffffffu, sum0, o);
            sum1 += __shfl_xor_sync(0xffffffffu, sum1, o);
        }
        if (tig == 0) {
            smf[ORDS + wni * 64 + row0] = sum0;
            smf[ORDS + wni * 64 + row1] = sum1;
        }
#pragma unroll
        for (int ni = 0; ni < 4; ++ni) {
            acc_o[ni][0] *= al0; acc_o[ni][1] *= al0;
            acc_o[ni][2] *= al1; acc_o[ni][3] *= al1;
        }
        __syncthreads();   // #3: Ps + reds ready

        if (t < 64) {
            float mo = smf[ORM + t];
            float mn = fmaxf(fmaxf(mo, fmaxf(smf[ORDM + t], smf[ORDM + 64 + t])),
                             fmaxf(smf[ORDM + 128 + t], smf[ORDM + 192 + t]));
            float a  = exp2c(mo - mn);
            smf[ORL + t] = smf[ORL + t] * a
                         + smf[ORDS + t] + smf[ORDS + 64 + t]
                         + smf[ORDS + 128 + t] + smf[ORDS + 192 + t];
            smf[ORM + t] = mn;
        }

        // ---- P·V (tf32 mma) ----
        const uint32_t* Pu = (const uint32_t*)(smf + OPS);
        const uint32_t* Vu = (const uint32_t*)Vb;
#pragma unroll
        for (int ks = 0; ks < 8; ++ks) {
            const int k0 = ks * 8;
            uint32_t a[4], b[4][2];
            a[0] = Pu[row0 * FPADP + k0 + tig];
            a[1] = Pu[row1 * FPADP + k0 + tig];
            a[2] = Pu[row0 * FPADP + k0 + tig + 4];
            a[3] = Pu[row1 * FPADP + k0 + tig + 4];
#pragma unroll
            for (int ni = 0; ni < 4; ++ni) {
                const int c = wd + ni * 8 + gid;
                b[ni][0] = Vu[(k0 + tig) * FPADV + c];
                b[ni][1] = Vu[(k0 + tig + 4) * FPADV + c];
            }
#pragma unroll
            for (int ni = 0; ni < 4; ++ni)
                mma16n8k8(acc_o[ni], a, b[ni]);
        }
    }

    __syncthreads();
    const float l0 = 1.f / smf[ORL + row0];
    const float l1 = 1.f / smf[ORL + row1];
    const int bb = bh >> 4;
    const int h  = bh & 15;
    float* o0 = attn + ((size_t)(bb * SEQ + grow0)) * HIDDEN + h * HEAD_DIM;
    float* o1 = attn + ((size_t)(bb * SEQ + grow1)) * HIDDEN + h * HEAD_DIM;
#pragma unroll
    for (int ni = 0; ni < 4; ++ni) {
        const int d = wd + ni * 8 + 2 * tig;
        float2 w0 = {to_tf32(acc_o[ni][0] * l0), to_tf32(acc_o[ni][1] * l0)};
        float2 w1 = {to_tf32(acc_o[ni][2] * l1), to_tf32(acc_o[ni][3] * l1)};
        *(float2*)(o0 + d) = w0;
        *(float2*)(o1 + d) = w1;
    }
}

// ============================================================================
// host launcher
// ============================================================================
extern "C" void kernel_launch(void* const* d_in, const int* in_sizes, int n_in,
                              void* d_out, int out_size)
{
    const float* x   = (const float*)d_in[0];
    const float* pm  = (const float*)d_in[1];
    const float* pol = (const float*)d_in[2];
    const float* mw  = (const float*)d_in[3];
    const float* Wq  = (const float*)d_in[4];
    const float* Wk  = (const float*)d_in[5];
    const float* Wv  = (const float*)d_in[6];
    const float* Wo  = (const float*)d_in[7];
    const float* bo  = (const float*)d_in[8];
    float* out = (float*)d_out;

    float *gq, *gk, *gv, *ga, *gw, *gx;
    cudaGetSymbolAddress((void**)&gq, g_q);
    cudaGetSymbolAddress((void**)&gk, g_k);
    cudaGetSymbolAddress((void**)&gv, g_v);
    cudaGetSymbolAddress((void**)&ga, g_attn);
    cudaGetSymbolAddress((void**)&gw, g_wc);
    cudaGetSymbolAddress((void**)&gx, g_xc);

    cudaFuncSetAttribute(flash_kernel,
                         cudaFuncAttributeMaxDynamicSharedMemorySize, FLASH_SMEM);
    cudaFuncSetAttribute(gemm_mma_kernel,
                         cudaFuncAttributeMaxDynamicSharedMemorySize, GEMM_SMEM);

    float* wcq = gw;
    float* wck = gw + (size_t)HIDDEN * HIDDEN;
    float* wcv = gw + 2 * (size_t)HIDDEN * HIDDEN;
    float* wco = gw + 3 * (size_t)HIDDEN * HIDDEN;

    const int n4 = HIDDEN * HIDDEN / 4;
    cvt_tf32_kernel5<<<dim3((n4 + 255) / 256, 1, 5), 256>>>(
        x, Wq, Wk, Wv, Wo, gx, wcq, wck, wcv, wco, n4);

    // K1: QKV projections
    gemm_mma_kernel<<<dim3(HIDDEN / BN, MROWS / BM, 3), 256, GEMM_SMEM>>>(
        gx, wcq, wck, wcv, gq, gk, gv, nullptr, 1);

    // K2: RoPE + tf32 rounding of k, v
    int rope_n = BATCH * HEADS * SEQ * 64;
    rope_kernel<<<(rope_n + 255) / 256, 256>>>(gq, gk, gv);

    // K3: tensor-core flash attention (512 threads)
    dim3 gfl(SEQ / 64, BATCH * HEADS);
    flash_kernel<<<gfl, 512, FLASH_SMEM>>>(gq, gk, gv, pm, pol, mw, ga);

    // K4: output projection + bias
    gemm_mma_kernel<<<dim3(HIDDEN / BN, MROWS / BM, 1), 256, GEMM_SMEM>>>(
        ga, wco, wco, wco, out, out, out, bo, 0);
}

// round 8
// speedup vs baseline: 3.2639x; 1.0278x over previous
#include <cuda_runtime.h>
#include <math.h>
#include <stdint.h>

#define HIDDEN   2048
#define HEADS    16
#define HEAD_DIM 128
#define BATCH    2
#define SEQ      1024
#define MROWS    (BATCH*SEQ)

// ---------------- scratch (allocation-free: device globals) ----------------
__device__ float g_q[BATCH*HEADS*SEQ*HEAD_DIM];
__device__ float g_k[BATCH*HEADS*SEQ*HEAD_DIM];
__device__ float g_v[BATCH*HEADS*SEQ*HEAD_DIM];
__device__ float g_attn[MROWS*HIDDEN];
__device__ float g_xc[MROWS*HIDDEN];        // tf32-rounded x
__device__ float g_wc[4*HIDDEN*HIDDEN];     // tf32-rounded weights, [K,N] layout

// ============================================================================
// helpers
// ============================================================================
__device__ __forceinline__ uint32_t smem_u32(const void* p) {
    uint32_t a;
    asm("{ .reg .u64 t; cvta.to.shared.u64 t, %1; cvt.u32.u64 %0, t; }"
        : "=r"(a) : "l"(p));
    return a;
}
__device__ __forceinline__ float to_tf32(float x) {
    uint32_t u;
    asm("cvt.rna.tf32.f32 %0, %1;" : "=r"(u) : "f"(x));
    return __uint_as_float(u);
}
__device__ __forceinline__ void cpa16(uint32_t s, const void* g) {
    asm volatile("cp.async.cg.shared.global [%0], [%1], 16;" :: "r"(s), "l"(g));
}
#define CPA_COMMIT() asm volatile("cp.async.commit_group;" ::: "memory")
template<int N> __device__ __forceinline__ void cpa_wait() {
    asm volatile("cp.async.wait_group %0;" :: "n"(N) : "memory");
}
__device__ __forceinline__ void mma16n8k8(float* c, const uint32_t* a, const uint32_t* b) {
    asm volatile(
        "mma.sync.aligned.m16n8k8.row.col.f32.tf32.tf32.f32 "
        "{%0,%1,%2,%3}, {%4,%5,%6,%7}, {%8,%9}, {%0,%1,%2,%3};"
        : "+f"(c[0]), "+f"(c[1]), "+f"(c[2]), "+f"(c[3])
        : "r"(a[0]), "r"(a[1]), "r"(a[2]), "r"(a[3]), "r"(b[0]), "r"(b[1]));
}

// 2^x via FMA-pipe polynomial (no MUFU)
__device__ __forceinline__ float exp2c(float x) {
    x = fmaxf(x, -126.f);
    float fl = floorf(x);
    float f  = x - fl;
    int   i  = (int)fl;
    float r = 1.52527338e-5f;
    r = fmaf(r, f, 1.54035304e-4f);
    r = fmaf(r, f, 1.33335581e-3f);
    r = fmaf(r, f, 9.61812911e-3f);
    r = fmaf(r, f, 5.55041087e-2f);
    r = fmaf(r, f, 2.40226507e-1f);
    r = fmaf(r, f, 6.93147181e-1f);
    r = fmaf(r, f, 1.0f);
    return r * __int_as_float((i + 127) << 23);
}
// log2(1+u) for u in [0, ~0.101]
__device__ __forceinline__ float log2p_small(float u) {
    float r = 0.14285714f;
    r = fmaf(r, u, -0.16666667f);
    r = fmaf(r, u, 0.2f);
    r = fmaf(r, u, -0.25f);
    r = fmaf(r, u, 0.33333333f);
    r = fmaf(r, u, -0.5f);
    r = fmaf(r, u, 1.0f);
    return r * u * 1.4426950408889634f;
}

// ============================================================================
// K0: elementwise tf32 rounding, 5 tensors in one launch (z-grid)
// ============================================================================
__global__ void cvt_tf32_kernel5(
    const float* __restrict__ s0, const float* __restrict__ s1,
    const float* __restrict__ s2, const float* __restrict__ s3,
    const float* __restrict__ s4,
    float* __restrict__ d0, float* __restrict__ d1,
    float* __restrict__ d2, float* __restrict__ d3,
    float* __restrict__ d4, int n4)
{
    int z = blockIdx.z;
    const float* src = (z == 0) ? s0 : (z == 1) ? s1 : (z == 2) ? s2 : (z == 3) ? s3 : s4;
    float* dst       = (z == 0) ? d0 : (z == 1) ? d1 : (z == 2) ? d2 : (z == 3) ? d3 : d4;
    int i = blockIdx.x * blockDim.x + threadIdx.x;
    if (i >= n4) return;
    float4 v = ((const float4*)src)[i];
    v.x = to_tf32(v.x); v.y = to_tf32(v.y); v.z = to_tf32(v.z); v.w = to_tf32(v.w);
    ((float4*)dst)[i] = v;
}

// ============================================================================
// K1/K4: tf32 mma.sync GEMM. C = A[2048x2048] * W[K,N] (+bias)
// CTA 128x128, BK=32, 4 warps (warp tile 64x64), cp.async 3-stage.
// ============================================================================
#define BM 128
#define BN 128
#define BK 32
#define PADK 36
#define PADN 136
#define ASTAGE (BM*PADK)
#define BSTAGE (BK*PADN)
#define NKT (HIDDEN / BK)
#define STAGE_FLOATS (ASTAGE + BSTAGE)
#define NSTAGE 3
#define GEMM_SMEM (NSTAGE * STAGE_FLOATS * 4)

__global__ __launch_bounds__(128, 2) void gemm_mma_kernel(
    const float* __restrict__ A,
    const float* __restrict__ B0, const float* __restrict__ B1, const float* __restrict__ B2,
    float* __restrict__ D0, float* __restrict__ D1, float* __restrict__ D2,
    const float* __restrict__ bias, int mode)
{
    extern __shared__ float sm[];
    const int t    = threadIdx.x;
    const int wid  = t >> 5;
    const int lane = t & 31;
    const int gid  = lane >> 2;
    const int tig  = lane & 3;
    const int z = blockIdx.z;
    const float* __restrict__ B = (z == 0) ? B0 : (z == 1) ? B1 : B2;
    float* __restrict__ D       = (z == 0) ? D0 : (z == 1) ? D1 : D2;
    const int n0 = blockIdx.x * BN;
    const int m0 = blockIdx.y * BM;
    const int wm = (wid & 1) * 64;
    const int wn = (wid >> 1) * 64;

    const uint32_t smb = smem_u32(sm);

    const int ar = t >> 3;
    const int ac = (t & 7) * 4;
    const float* agp = A + (size_t)(m0 + ar) * HIDDEN + ac;
    const uint32_t asb = smb + (uint32_t)(ar * PADK + ac) * 4;
    const int br = t >> 5;
    const int bc = (t & 31) * 4;
    const float* bgp = B + (size_t)br * HIDDEN + n0 + bc;
    const uint32_t bsb = smb + (uint32_t)(ASTAGE + br * PADN + bc) * 4;

    float acc[4][8][4];
#pragma unroll
    for (int mi = 0; mi < 4; ++mi)
#pragma unroll
        for (int ni = 0; ni < 8; ++ni)
#pragma unroll
            for (int j = 0; j < 4; ++j) acc[mi][ni][j] = 0.f;

    auto issue = [&](int kt, int s) {
        const uint32_t so = (uint32_t)(s * STAGE_FLOATS) * 4;
        const int ko = kt * BK;
#pragma unroll
        for (int i = 0; i < 8; ++i)
            cpa16(asb + so + (uint32_t)(i * 16 * PADK) * 4, agp + (size_t)i * 16 * HIDDEN + ko);
#pragma unroll
        for (int i = 0; i < 8; ++i)
            cpa16(bsb + so + (uint32_t)(i * 4 * PADN) * 4, bgp + (size_t)(i * 4 + ko) * HIDDEN);
        CPA_COMMIT();
    };

    issue(0, 0);
    issue(1, 1);

    int cs = 0;
    int is = 2;

    for (int kt = 0; kt < NKT; ++kt) {
        cpa_wait<1>();
        __syncthreads();

        if (kt + 2 < NKT) issue(kt + 2, is);
        else              CPA_COMMIT();
        is = (is == 2) ? 0 : is + 1;

        const uint32_t* Asu = (const uint32_t*)(sm + cs * STAGE_FLOATS);
        const uint32_t* Bsu = Asu + ASTAGE;
        cs = (cs == 2) ? 0 : cs + 1;

#pragma unroll
        for (int ks = 0; ks < 4; ++ks) {
            const int k0 = ks * 8;
            uint32_t a[4][4], b[8][2];
#pragma unroll
            for (int mi = 0; mi < 4; ++mi) {
                const int r = wm + mi * 16 + gid;
                a[mi][0] = Asu[r * PADK + k0 + tig];
                a[mi][1] = Asu[(r + 8) * PADK + k0 + tig];
                a[mi][2] = Asu[r * PADK + k0 + tig + 4];
                a[mi][3] = Asu[(r + 8) * PADK + k0 + tig + 4];
            }
#pragma unroll
            for (int ni = 0; ni < 8; ++ni) {
                const int c = wn + ni * 8 + gid;
                b[ni][0] = Bsu[(k0 + tig) * PADN + c];
                b[ni][1] = Bsu[(k0 + tig + 4) * PADN + c];
            }
#pragma unroll
            for (int mi = 0; mi < 4; ++mi)
#pragma unroll
                for (int ni = 0; ni < 8; ++ni)
                    mma16n8k8(acc[mi][ni], a[mi], b[ni]);
        }
    }

#pragma unroll
    for (int mi = 0; mi < 4; ++mi) {
#pragma unroll
        for (int ni = 0; ni < 8; ++ni) {
            const int c = wn + ni * 8 + 2 * tig;
            const int r0 = wm + mi * 16 + gid;
            const int r1 = r0 + 8;
            float2 v0 = {acc[mi][ni][0], acc[mi][ni][1]};
            float2 v1 = {acc[mi][ni][2], acc[mi][ni][3]};
            if (mode == 0) {
                float2 bb = *(const float2*)&bias[n0 + c];
                v0.x += bb.x; v0.y += bb.y;
                v1.x += bb.x; v1.y += bb.y;
                *(float2*)&D[(size_t)(m0 + r0) * HIDDEN + n0 + c] = v0;
                *(float2*)&D[(size_t)(m0 + r1) * HIDDEN + n0 + c] = v1;
            } else {
                const int h = blockIdx.x;     // BN == HEAD_DIM
                int m = m0 + r0;
                int bb0 = m >> 10, s0q = m & 1023;
                *(float2*)&D[(((size_t)(bb0 * HEADS + h) * SEQ + s0q) << 7) + c] = v0;
                m = m0 + r1;
                int bb1 = m >> 10, s1q = m & 1023;
                *(float2*)&D[(((size_t)(bb1 * HEADS + h) * SEQ + s1q) << 7) + c] = v1;
            }
        }
    }
}

// ============================================================================
// K2: RoPE in place on q,k; k,v rounded to tf32 (flash MMA operands)
// ============================================================================
__global__ void rope_kernel(float* __restrict__ q, float* __restrict__ k, float* __restrict__ v)
{
    int idx = blockIdx.x * blockDim.x + threadIdx.x;
    if (idx >= BATCH * HEADS * SEQ * 64) return;
    int i  = idx & 63;
    int s  = (idx >> 6) & (SEQ - 1);
    int bh = idx >> 16;

    float inv = expf(-(float)(2 * i) * (9.210340371976184f / 128.f));
    float th  = (float)s * inv;
    float sn, cs;
    sincosf(th, &sn, &cs);

    size_t base = ((size_t)bh * SEQ + s) * HEAD_DIM + i;
    float q1 = q[base], q2 = q[base + 64];
    q[base]      = q1 * cs - q2 * sn;
    q[base + 64] = q2 * cs + q1 * sn;
    float k1 = k[base], k2 = k[base + 64];
    k[base]      = to_tf32(k1 * cs - k2 * sn);
    k[base + 64] = to_tf32(k2 * cs + k1 * sn);
    v[base]      = to_tf32(v[base]);
    v[base + 64] = to_tf32(v[base + 64]);
}

// ============================================================================
// K3: causal flash attention, tf32 mma.sync, fused bias, log2 softmax.
// RACE FIX: next-tile KV cp.async is issued AFTER sync #1 (the overwritten
// buffer was last read in iteration jt-1; sync #1 orders all warps past it).
// ============================================================================
#define FPADD 132
#define FPADV 136
#define FPADP 68
#define OQH  0
#define OQL  8448
#define OKS  16896
#define OVS  33792
#define OPS  51200
#define ORM  55552
#define ORL  55616
#define ORDM 55680
#define ORDS 55936
#define FLASH_FLOATS 56192
#define FLASH_SMEM (FLASH_FLOATS * 4)

__global__ __launch_bounds__(512, 1) void flash_kernel(
    const float* __restrict__ q, const float* __restrict__ k, const float* __restrict__ v,
    const float* __restrict__ pm, const float* __restrict__ pol, const float* __restrict__ mw,
    float* __restrict__ attn)
{
    extern __shared__ float smf[];
    const uint32_t smb = smem_u32(smf);

    const int t    = threadIdx.x;
    const int wid  = t >> 5;
    const int lane = t & 31;
    const int gid  = lane >> 2;
    const int tig  = lane & 3;
    const int wm   = (wid & 3) * 16;
    const int wni  = wid >> 2;
    const int wn   = wni * 16;
    const int wd   = wni * 32;

    const int qt = (gridDim.x - 1) - blockIdx.x;
    const int bh = blockIdx.y;
    const int q0 = qt * 64;

    const float* qb = q + (size_t)bh * SEQ * HEAD_DIM;
    const float* kb = k + (size_t)bh * SEQ * HEAD_DIM;
    const float* vb = v + (size_t)bh * SEQ * HEAD_DIM;
    const size_t moff = (size_t)bh * SEQ * SEQ;

    for (int idx = t; idx < 64 * 32; idx += 512) {
        int r  = idx >> 5;
        int c4 = (idx & 31) * 4;
        float4 x = *(const float4*)&qb[(size_t)(q0 + r) * HEAD_DIM + c4];
        float* qh = smf + OQH + r * FPADD + c4;
        float* ql = smf + OQL + r * FPADD + c4;
        float h0 = to_tf32(x.x); qh[0] = h0; ql[0] = to_tf32(x.x - h0);
        float h1 = to_tf32(x.y); qh[1] = h1; ql[1] = to_tf32(x.y - h1);
        float h2 = to_tf32(x.z); qh[2] = h2; ql[2] = to_tf32(x.z - h2);
        float h3 = to_tf32(x.w); qh[3] = h3; ql[3] = to_tf32(x.w - h3);
    }
    if (t < 64) { smf[ORM + t] = -1e30f; smf[ORL + t] = 0.f; }

    auto issueKV = [&](int jt, int s) {
        const int j0 = jt * 64;
#pragma unroll
        for (int i = 0; i < 4; ++i) {
            int idx = i * 512 + t;
            int r  = idx >> 5;
            int c4 = (idx & 31) * 4;
            const float* kg = &kb[(size_t)(j0 + r) * HEAD_DIM + c4];
            const float* vg = &vb[(size_t)(j0 + r) * HEAD_DIM + c4];
            cpa16(smb + (uint32_t)(OKS + s * 8448 + r * FPADD + c4) * 4, kg);
            cpa16(smb + (uint32_t)(OVS + s * 8704 + r * FPADV + c4) * 4, vg);
        }
        CPA_COMMIT();
    };

    issueKV(0, 0);

    const float SC2  = 0.08838834764831845f * 1.4426950408889634f;
    const float CPM  = 0.05f * 1.4426950408889634f;
    const float CPO  = 0.1f  * 1.4426950408889634f;

    const int row0  = wm + gid;
    const int row1  = row0 + 8;
    const int grow0 = q0 + row0;
    const int grow1 = q0 + row1;

    float acc_o[4][4];
#pragma unroll
    for (int ni = 0; ni < 4; ++ni)
#pragma unroll
        for (int j = 0; j < 4; ++j) acc_o[ni][j] = 0.f;

    for (int jt = 0; jt <= qt; ++jt) {
        cpa_wait<0>();     // stage jt fully arrived (group jt is last issued)
        __syncthreads();   // #1: all warps done with iteration jt-1 (buffers free)

        // SAFE: buffer (jt+1)&1 was last read in iteration jt-1; every warp is
        // past sync #1, so the async overwrite cannot race a reader.
        if (jt < qt) issueKV(jt + 1, (jt + 1) & 1);

        const float* Kb = smf + OKS + (jt & 1) * 8448;
        const float* Vb = smf + OVS + (jt & 1) * 8704;
        const int j0c = jt * 64;

        const size_t mr0 = moff + (size_t)grow0 * SEQ + j0c;
        const size_t mr1 = moff + (size_t)grow1 * SEQ + j0c;
        float2 pa0[2], pb0[2], pc0[2], pa1[2], pb1[2], pc1[2];
#pragma unroll
        for (int ni = 0; ni < 2; ++ni) {
            const int cl = wn + ni * 8 + 2 * tig;
            pa0[ni] = *(const float2*)&pm[mr0 + cl];
            pb0[ni] = *(const float2*)&pol[mr0 + cl];
            pc0[ni] = *(const float2*)&mw[mr0 + cl];
            pa1[ni] = *(const float2*)&pm[mr1 + cl];
            pb1[ni] = *(const float2*)&pol[mr1 + cl];
            pc1[ni] = *(const float2*)&mw[mr1 + cl];
        }

        float accs[2][4];
#pragma unroll
        for (int ni = 0; ni < 2; ++ni)
#pragma unroll
            for (int j = 0; j < 4; ++j) accs[ni][j] = 0.f;

#pragma unroll
        for (int ks = 0; ks < 16; ++ks) {
            const int k0 = ks * 8;
            uint32_t ah[4], al[4], b[2][2];
            const uint32_t* Qh = (const uint32_t*)(smf + OQH);
            const uint32_t* Ql = (const uint32_t*)(smf + OQL);
            ah[0] = Qh[row0 * FPADD + k0 + tig];
            ah[1] = Qh[row1 * FPADD + k0 + tig];
            ah[2] = Qh[row0 * FPADD + k0 + tig + 4];
            ah[3] = Qh[row1 * FPADD + k0 + tig + 4];
            al[0] = Ql[row0 * FPADD + k0 + tig];
            al[1] = Ql[row1 * FPADD + k0 + tig];
            al[2] = Ql[row0 * FPADD + k0 + tig + 4];
            al[3] = Ql[row1 * FPADD + k0 + tig + 4];
            const uint32_t* Ku = (const uint32_t*)Kb;
#pragma unroll
            for (int ni = 0; ni < 2; ++ni) {
                const int c = wn + ni * 8 + gid;
                b[ni][0] = Ku[c * FPADD + k0 + tig];
                b[ni][1] = Ku[c * FPADD + k0 + tig + 4];
            }
#pragma unroll
            for (int ni = 0; ni < 2; ++ni) {
                mma16n8k8(accs[ni], ah, b[ni]);
                mma16n8k8(accs[ni], al, b[ni]);
            }
        }

        const bool diag = (jt == qt);
        float ml0 = -1e30f, ml1 = -1e30f;
#pragma unroll
        for (int ni = 0; ni < 2; ++ni) {
            const int cl = wn + ni * 8 + 2 * tig;
            float s0 = fmaf(accs[ni][0], SC2, fmaf(pa0[ni].x, CPM, fmaf(pb0[ni].x, CPO, log2p_small(fmaf(pc0[ni].x, 0.1f, 1e-8f)))));
            float s1 = fmaf(accs[ni][1], SC2, fmaf(pa0[ni].y, CPM, fmaf(pb0[ni].y, CPO, log2p_small(fmaf(pc0[ni].y, 0.1f, 1e-8f)))));
            float s2 = fmaf(accs[ni][2], SC2, fmaf(pa1[ni].x, CPM, fmaf(pb1[ni].x, CPO, log2p_small(fmaf(pc1[ni].x, 0.1f, 1e-8f)))));
            float s3 = fmaf(accs[ni][3], SC2, fmaf(pa1[ni].y, CPM, fmaf(pb1[ni].y, CPO, log2p_small(fmaf(pc1[ni].y, 0.1f, 1e-8f)))));
            if (diag) {
                if (cl     > row0) s0 = -1e30f;
                if (cl + 1 > row0) s1 = -1e30f;
                if (cl     > row1) s2 = -1e30f;
                if (cl + 1 > row1) s3 = -1e30f;
            }
            accs[ni][0] = s0; accs[ni][1] = s1; accs[ni][2] = s2; accs[ni][3] = s3;
            ml0 = fmaxf(ml0, fmaxf(s0, s1));
            ml1 = fmaxf(ml1, fmaxf(s2, s3));
        }
#pragma unroll
        for (int o = 1; o < 4; o <<= 1) {
            ml0 = fmaxf(ml0, __shfl_xor_sync(0xffffffffu, ml0, o));
            ml1 = fmaxf(ml1, __shfl_xor_sync(0xffffffffu, ml1, o));
        }
        if (tig == 0) {
            smf[ORDM + wni * 64 + row0] = ml0;
            smf[ORDM + wni * 64 + row1] = ml1;
        }
        float mold0 = smf[ORM + row0];
        float mold1 = smf[ORM + row1];
        __syncthreads();   // #2: redm ready

        float mn0 = fmaxf(fmaxf(mold0, fmaxf(smf[ORDM + row0], smf[ORDM + 64 + row0])),
                          fmaxf(smf[ORDM + 128 + row0], smf[ORDM + 192 + row0]));
        float mn1 = fmaxf(fmaxf(mold1, fmaxf(smf[ORDM + row1], smf[ORDM + 64 + row1])),
                          fmaxf(smf[ORDM + 128 + row1], smf[ORDM + 192 + row1]));
        float al0 = exp2c(mold0 - mn0);
        float al1 = exp2c(mold1 - mn1);

        float sum0 = 0.f, sum1 = 0.f;
#pragma unroll
        for (int ni = 0; ni < 2; ++ni) {
            const int cl = wn + ni * 8 + 2 * tig;
            float p0 = exp2c(accs[ni][0] - mn0);
            float p1 = exp2c(accs[ni][1] - mn0);
            float p2 = exp2c(accs[ni][2] - mn1);
            float p3 = exp2c(accs[ni][3] - mn1);
            sum0 += p0 + p1;
            sum1 += p2 + p3;
            smf[OPS + row0 * FPADP + cl]     = to_tf32(p0);
            smf[OPS + row0 * FPADP + cl + 1] = to_tf32(p1);
            smf[OPS + row1 * FPADP + cl]     = to_tf32(p2);
            smf[OPS + row1 * FPADP + cl + 1] = to_tf32(p3);
        }
#pragma unroll
        for (int o = 1; o < 4; o <<= 1) {
            sum0 += __shfl_xor_sync(0xffffffffu, sum0, o);
            sum1 += __shfl_xor_sync(0xffffffffu, sum1, o);
        }
        if (tig == 0) {
            smf[ORDS + wni * 64 + row0] = sum0;
            smf[ORDS + wni * 64 + row1] = sum1;
        }
#pragma unroll
        for (int ni = 0; ni < 4; ++ni) {
            acc_o[ni][0] *= al0; acc_o[ni][1] *= al0;
            acc_o[ni][2] *= al1; acc_o[ni][3] *= al1;
        }
        __syncthreads();   // #3: Ps + reds ready

        if (t < 64) {
            float mo = smf[ORM + t];
            float mn = fmaxf(fmaxf(mo, fmaxf(smf[ORDM + t], smf[ORDM + 64 + t])),
                             fmaxf(smf[ORDM + 128 + t], smf[ORDM + 192 + t]));
            float a  = exp2c(mo - mn);
            smf[ORL + t] = smf[ORL + t] * a
                         + smf[ORDS + t] + smf[ORDS + 64 + t]
                         + smf[ORDS + 128 + t] + smf[ORDS + 192 + t];
            smf[ORM + t] = mn;
        }

        const uint32_t* Pu = (const uint32_t*)(smf + OPS);
        const uint32_t* Vu = (const uint32_t*)Vb;
#pragma unroll
        for (int ks = 0; ks < 8; ++ks) {
            const int k0 = ks * 8;
            uint32_t a[4], b[4][2];
            a[0] = Pu[row0 * FPADP + k0 + tig];
            a[1] = Pu[row1 * FPADP + k0 + tig];
            a[2] = Pu[row0 * FPADP + k0 + tig + 4];
            a[3] = Pu[row1 * FPADP + k0 + tig + 4];
#pragma unroll
            for (int ni = 0; ni < 4; ++ni) {
                const int c = wd + ni * 8 + gid;
                b[ni][0] = Vu[(k0 + tig) * FPADV + c];
                b[ni][1] = Vu[(k0 + tig + 4) * FPADV + c];
            }
#pragma unroll
            for (int ni = 0; ni < 4; ++ni)
                mma16n8k8(acc_o[ni], a, b[ni]);
        }
    }

    __syncthreads();
    const float l0 = 1.f / smf[ORL + row0];
    const float l1 = 1.f / smf[ORL + row1];
    const int bb = bh >> 4;
    const int h  = bh & 15;
    float* o0 = attn + ((size_t)(bb * SEQ + grow0)) * HIDDEN + h * HEAD_DIM;
    float* o1 = attn + ((size_t)(bb * SEQ + grow1)) * HIDDEN + h * HEAD_DIM;
#pragma unroll
    for (int ni = 0; ni < 4; ++ni) {
        const int d = wd + ni * 8 + 2 * tig;
        float2 w0 = {to_tf32(acc_o[ni][0] * l0), to_tf32(acc_o[ni][1] * l0)};
        float2 w1 = {to_tf32(acc_o[ni][2] * l1), to_tf32(acc_o[ni][3] * l1)};
        *(float2*)(o0 + d) = w0;
        *(float2*)(o1 + d) = w1;
    }
}

// ============================================================================
// host launcher
// ============================================================================
extern "C" void kernel_launch(void* const* d_in, const int* in_sizes, int n_in,
                              void* d_out, int out_size)
{
    const float* x   = (const float*)d_in[0];
    const float* pm  = (const float*)d_in[1];
    const float* pol = (const float*)d_in[2];
    const float* mw  = (const float*)d_in[3];
    const float* Wq  = (const float*)d_in[4];
    const float* Wk  = (const float*)d_in[5];
    const float* Wv  = (const float*)d_in[6];
    const float* Wo  = (const float*)d_in[7];
    const float* bo  = (const float*)d_in[8];
    float* out = (float*)d_out;

    float *gq, *gk, *gv, *ga, *gw, *gx;
    cudaGetSymbolAddress((void**)&gq, g_q);
    cudaGetSymbolAddress((void**)&gk, g_k);
    cudaGetSymbolAddress((void**)&gv, g_v);
    cudaGetSymbolAddress((void**)&ga, g_attn);
    cudaGetSymbolAddress((void**)&gw, g_wc);
    cudaGetSymbolAddress((void**)&gx, g_xc);

    cudaFuncSetAttribute(flash_kernel,
                         cudaFuncAttributeMaxDynamicSharedMemorySize, FLASH_SMEM);
    cudaFuncSetAttribute(gemm_mma_kernel,
                         cudaFuncAttributeMaxDynamicSharedMemorySize, GEMM_SMEM);

    float* wcq = gw;
    float* wck = gw + (size_t)HIDDEN * HIDDEN;
    float* wcv = gw + 2 * (size_t)HIDDEN * HIDDEN;
    float* wco = gw + 3 * (size_t)HIDDEN * HIDDEN;

    const int n4 = HIDDEN * HIDDEN / 4;
    cvt_tf32_kernel5<<<dim3((n4 + 255) / 256, 1, 5), 256>>>(
        x, Wq, Wk, Wv, Wo, gx, wcq, wck, wcv, wco, n4);

    // K1: QKV projections (4-warp, 64x64 warp-tile GEMM)
    gemm_mma_kernel<<<dim3(HIDDEN / BN, MROWS / BM, 3), 128, GEMM_SMEM>>>(
        gx, wcq, wck, wcv, gq, gk, gv, nullptr, 1);

    // K2: RoPE + tf32 rounding of k, v
    int rope_n = BATCH * HEADS * SEQ * 64;
    rope_kernel<<<(rope_n + 255) / 256, 256>>>(gq, gk, gv);

    // K3: tensor-core flash attention (512 threads, race-fixed KV pipeline)
    dim3 gfl(SEQ / 64, BATCH * HEADS);
    flash_kernel<<<gfl, 512, FLASH_SMEM>>>(gq, gk, gv, pm, pol, mw, ga);

    // K4: output projection + bias
    gemm_mma_kernel<<<dim3(HIDDEN / BN, MROWS / BM, 1), 128, GEMM_SMEM>>>(
        ga, wco, wco, wco, out, out, out, bo, 0);
}

// round 9
// speedup vs baseline: 3.3573x; 1.0286x over previous
#include <cuda_runtime.h>
#include <math.h>
#include <stdint.h>

#define HIDDEN   2048
#define HEADS    16
#define HEAD_DIM 128
#define BATCH    2
#define SEQ      1024
#define MROWS    (BATCH*SEQ)

// ---------------- scratch (allocation-free: device globals) ----------------
__device__ float g_q[BATCH*HEADS*SEQ*HEAD_DIM];
__device__ float g_k[BATCH*HEADS*SEQ*HEAD_DIM];
__device__ float g_v[BATCH*HEADS*SEQ*HEAD_DIM];
__device__ float g_attn[MROWS*HIDDEN];
__device__ float g_xc[MROWS*HIDDEN];        // tf32-rounded x
__device__ float g_wt[4*HIDDEN*HIDDEN];     // tf32-rounded transposed weights [N,K]

// ============================================================================
// helpers
// ============================================================================
__device__ __forceinline__ uint32_t smem_u32(const void* p) {
    uint32_t a;
    asm("{ .reg .u64 t; cvta.to.shared.u64 t, %1; cvt.u32.u64 %0, t; }"
        : "=r"(a) : "l"(p));
    return a;
}
__device__ __forceinline__ float to_tf32(float x) {
    uint32_t u;
    asm("cvt.rna.tf32.f32 %0, %1;" : "=r"(u) : "f"(x));
    return __uint_as_float(u);
}
__device__ __forceinline__ void cpa16(uint32_t s, const void* g) {
    asm volatile("cp.async.cg.shared.global [%0], [%1], 16;" :: "r"(s), "l"(g));
}
#define CPA_COMMIT() asm volatile("cp.async.commit_group;" ::: "memory")
template<int N> __device__ __forceinline__ void cpa_wait() {
    asm volatile("cp.async.wait_group %0;" :: "n"(N) : "memory");
}
__device__ __forceinline__ void mma16n8k8(float* c, const uint32_t* a, const uint32_t* b) {
    asm volatile(
        "mma.sync.aligned.m16n8k8.row.col.f32.tf32.tf32.f32 "
        "{%0,%1,%2,%3}, {%4,%5,%6,%7}, {%8,%9}, {%0,%1,%2,%3};"
        : "+f"(c[0]), "+f"(c[1]), "+f"(c[2]), "+f"(c[3])
        : "r"(a[0]), "r"(a[1]), "r"(a[2]), "r"(a[3]), "r"(b[0]), "r"(b[1]));
}

// 2^x via FMA-pipe polynomial (no MUFU)
__device__ __forceinline__ float exp2c(float x) {
    x = fmaxf(x, -126.f);
    float fl = floorf(x);
    float f  = x - fl;
    int   i  = (int)fl;
    float r = 1.52527338e-5f;
    r = fmaf(r, f, 1.54035304e-4f);
    r = fmaf(r, f, 1.33335581e-3f);
    r = fmaf(r, f, 9.61812911e-3f);
    r = fmaf(r, f, 5.55041087e-2f);
    r = fmaf(r, f, 2.40226507e-1f);
    r = fmaf(r, f, 6.93147181e-1f);
    r = fmaf(r, f, 1.0f);
    return r * __int_as_float((i + 127) << 23);
}
// log2(1+u) for u in [0, ~0.101]
__device__ __forceinline__ float log2p_small(float u) {
    float r = 0.14285714f;
    r = fmaf(r, u, -0.16666667f);
    r = fmaf(r, u, 0.2f);
    r = fmaf(r, u, -0.25f);
    r = fmaf(r, u, 0.33333333f);
    r = fmaf(r, u, -0.5f);
    r = fmaf(r, u, 1.0f);
    return r * u * 1.4426950408889634f;
}

// ============================================================================
// K0a: weight transpose + tf32 round: W[K,N] -> Wt[N,K], 4 matrices (z-grid)
// ============================================================================
__global__ void transpose2048(const float* __restrict__ s0, const float* __restrict__ s1,
                              const float* __restrict__ s2, const float* __restrict__ s3,
                              float* __restrict__ dst)
{
    __shared__ float tile[32][33];
    int z = blockIdx.z;
    const float* src = (z == 0) ? s0 : (z == 1) ? s1 : (z == 2) ? s2 : s3;
    float* d = dst + (size_t)z * HIDDEN * HIDDEN;
    int tx = threadIdx.x & 31, ty = threadIdx.x >> 5;
    int x  = blockIdx.x * 32 + tx, y0 = blockIdx.y * 32 + ty;
#pragma unroll
    for (int j = 0; j < 4; ++j)
        tile[ty + j * 8][tx] = to_tf32(src[(size_t)(y0 + j * 8) * HIDDEN + x]);
    __syncthreads();
    int x2 = blockIdx.y * 32 + tx, y2 = blockIdx.x * 32 + ty;
#pragma unroll
    for (int j = 0; j < 4; ++j)
        d[(size_t)(y2 + j * 8) * HIDDEN + x2] = tile[tx][ty + j * 8];
}

// ============================================================================
// K0b: elementwise tf32 rounding (x only)
// ============================================================================
__global__ void cvt_tf32_kernel(const float* __restrict__ src, float* __restrict__ dst, int n4)
{
    int i = blockIdx.x * blockDim.x + threadIdx.x;
    if (i >= n4) return;
    float4 v = ((const float4*)src)[i];
    v.x = to_tf32(v.x); v.y = to_tf32(v.y); v.z = to_tf32(v.z); v.w = to_tf32(v.w);
    ((float4*)dst)[i] = v;
}

// ============================================================================
// K1/K4: tf32 mma.sync GEMM. C = A[M,K] * Wt[N,K]^T (+bias)
// CTA 128x128, BK=32, 4 warps (64x64), 2-stage cp.async (race-safe order),
// LDS.64 fragment loads via k-slice permutation (slice tig <-> k=2tig,2tig+1).
// ============================================================================
#define BM 128
#define BN 128
#define BK 32
#define PADK 40
#define ASTAGE (BM*PADK)
#define BSTAGE (BN*PADK)
#define NKT (HIDDEN / BK)
#define STAGE_FLOATS (ASTAGE + BSTAGE)
#define NSTAGE 2
#define GEMM_SMEM (NSTAGE * STAGE_FLOATS * 4)

__global__ __launch_bounds__(128, 2) void gemm_mma_kernel(
    const float* __restrict__ A,
    const float* __restrict__ B0, const float* __restrict__ B1, const float* __restrict__ B2,
    float* __restrict__ D0, float* __restrict__ D1, float* __restrict__ D2,
    const float* __restrict__ bias, int mode)
{
    extern __shared__ float sm[];
    const int t    = threadIdx.x;
    const int wid  = t >> 5;
    const int lane = t & 31;
    const int gid  = lane >> 2;
    const int tig  = lane & 3;
    const int z = blockIdx.z;
    const float* __restrict__ B = (z == 0) ? B0 : (z == 1) ? B1 : B2;
    float* __restrict__ D       = (z == 0) ? D0 : (z == 1) ? D1 : D2;
    const int n0 = blockIdx.x * BN;
    const int m0 = blockIdx.y * BM;
    const int wm = (wid & 1) * 64;
    const int wn = (wid >> 1) * 64;

    const uint32_t smb = smem_u32(sm);

    // cp.async mappings: both strips are 128 rows x 32 k (k-contiguous)
    const int ar = t >> 3;           // 0..15 (+16 per iter)
    const int ac = (t & 7) * 4;
    const float* agp = A + (size_t)(m0 + ar) * HIDDEN + ac;
    const float* bgp = B + (size_t)(n0 + ar) * HIDDEN + ac;
    const uint32_t asb = smb + (uint32_t)(ar * PADK + ac) * 4;
    const uint32_t bsb = smb + (uint32_t)(ASTAGE + ar * PADK + ac) * 4;

    float acc[4][8][4];
#pragma unroll
    for (int mi = 0; mi < 4; ++mi)
#pragma unroll
        for (int ni = 0; ni < 8; ++ni)
#pragma unroll
            for (int j = 0; j < 4; ++j) acc[mi][ni][j] = 0.f;

    auto issue = [&](int kt, int s) {
        const uint32_t so = (uint32_t)(s * STAGE_FLOATS) * 4;
        const int ko = kt * BK;
#pragma unroll
        for (int i = 0; i < 8; ++i)
            cpa16(asb + so + (uint32_t)(i * 16 * PADK) * 4, agp + (size_t)i * 16 * HIDDEN + ko);
#pragma unroll
        for (int i = 0; i < 8; ++i)
            cpa16(bsb + so + (uint32_t)(i * 16 * PADK) * 4, bgp + (size_t)i * 16 * HIDDEN + ko);
        CPA_COMMIT();
    };

    issue(0, 0);

    for (int kt = 0; kt < NKT; ++kt) {
        cpa_wait<0>();       // stage kt fully arrived
        __syncthreads();     // all warps done reading stage kt-1 (== buffer (kt+1)&1)
        if (kt + 1 < NKT) issue(kt + 1, (kt + 1) & 1);   // safe: after barrier

        const float* As = sm + (kt & 1) * STAGE_FLOATS;
        const float* Bs = As + ASTAGE;

#pragma unroll
        for (int ks = 0; ks < 4; ++ks) {
            const int k0 = ks * 8;
            const int kk = k0 + 2 * tig;         // slice-permuted adjacent pair
            uint32_t a[4][4], b[8][2];
#pragma unroll
            for (int mi = 0; mi < 4; ++mi) {
                const int r = wm + mi * 16 + gid;
                uint2 v0 = *(const uint2*)&As[r * PADK + kk];
                uint2 v1 = *(const uint2*)&As[(r + 8) * PADK + kk];
                a[mi][0] = v0.x; a[mi][2] = v0.y;
                a[mi][1] = v1.x; a[mi][3] = v1.y;
            }
#pragma unroll
            for (int ni = 0; ni < 8; ++ni) {
                const int c = wn + ni * 8 + gid;
                uint2 v = *(const uint2*)&Bs[c * PADK + kk];
                b[ni][0] = v.x; b[ni][1] = v.y;
            }
#pragma unroll
            for (int mi = 0; mi < 4; ++mi)
#pragma unroll
                for (int ni = 0; ni < 8; ++ni)
                    mma16n8k8(acc[mi][ni], a[mi], b[ni]);
        }
    }

#pragma unroll
    for (int mi = 0; mi < 4; ++mi) {
#pragma unroll
        for (int ni = 0; ni < 8; ++ni) {
            const int c = wn + ni * 8 + 2 * tig;
            const int r0 = wm + mi * 16 + gid;
            const int r1 = r0 + 8;
            float2 v0 = {acc[mi][ni][0], acc[mi][ni][1]};
            float2 v1 = {acc[mi][ni][2], acc[mi][ni][3]};
            if (mode == 0) {
                float2 bb = *(const float2*)&bias[n0 + c];
                v0.x += bb.x; v0.y += bb.y;
                v1.x += bb.x; v1.y += bb.y;
                *(float2*)&D[(size_t)(m0 + r0) * HIDDEN + n0 + c] = v0;
                *(float2*)&D[(size_t)(m0 + r1) * HIDDEN + n0 + c] = v1;
            } else {
                const int h = blockIdx.x;     // BN == HEAD_DIM
                int m = m0 + r0;
                int bb0 = m >> 10, s0q = m & 1023;
                *(float2*)&D[(((size_t)(bb0 * HEADS + h) * SEQ + s0q) << 7) + c] = v0;
                m = m0 + r1;
                int bb1 = m >> 10, s1q = m & 1023;
                *(float2*)&D[(((size_t)(bb1 * HEADS + h) * SEQ + s1q) << 7) + c] = v1;
            }
        }
    }
}

// ============================================================================
// K2: RoPE in place on q,k; k,v rounded to tf32 (flash MMA operands)
// ============================================================================
__global__ void rope_kernel(float* __restrict__ q, float* __restrict__ k, float* __restrict__ v)
{
    int idx = blockIdx.x * blockDim.x + threadIdx.x;
    if (idx >= BATCH * HEADS * SEQ * 64) return;
    int i  = idx & 63;
    int s  = (idx >> 6) & (SEQ - 1);
    int bh = idx >> 16;

    float inv = expf(-(float)(2 * i) * (9.210340371976184f / 128.f));
    float th  = (float)s * inv;
    float sn, cs;
    sincosf(th, &sn, &cs);

    size_t base = ((size_t)bh * SEQ + s) * HEAD_DIM + i;
    float q1 = q[base], q2 = q[base + 64];
    q[base]      = q1 * cs - q2 * sn;
    q[base + 64] = q2 * cs + q1 * sn;
    float k1 = k[base], k2 = k[base + 64];
    k[base]      = to_tf32(k1 * cs - k2 * sn);
    k[base + 64] = to_tf32(k2 * cs + k1 * sn);
    v[base]      = to_tf32(v[base]);
    v[base + 64] = to_tf32(v[base + 64]);
}

// ============================================================================
// K3: causal flash attention, tf32 mma.sync, LDS.64 fragment loads.
// 512 threads, 16 warps (4m x 4n). Race-safe KV pipeline (issue after barrier).
// ============================================================================
#define FPADD 136
#define FPADV 132
#define FPADP 72
#define OQH  0
#define OQL  8704
#define OKS  17408
#define OVS  34816
#define OPS  51712
#define ORM  56320
#define ORL  56384
#define ORDM 56448
#define ORDS 56704
#define FLASH_FLOATS 56960
#define FLASH_SMEM (FLASH_FLOATS * 4)

__global__ __launch_bounds__(512, 1) void flash_kernel(
    const float* __restrict__ q, const float* __restrict__ k, const float* __restrict__ v,
    const float* __restrict__ pm, const float* __restrict__ pol, const float* __restrict__ mw,
    float* __restrict__ attn)
{
    extern __shared__ float smf[];
    const uint32_t smb = smem_u32(smf);

    const int t    = threadIdx.x;
    const int wid  = t >> 5;
    const int lane = t & 31;
    const int gid  = lane >> 2;
    const int tig  = lane & 3;
    const int wm   = (wid & 3) * 16;
    const int wni  = wid >> 2;
    const int wn   = wni * 16;
    const int wd   = wni * 32;

    const int qt = (gridDim.x - 1) - blockIdx.x;
    const int bh = blockIdx.y;
    const int q0 = qt * 64;

    const float* qb = q + (size_t)bh * SEQ * HEAD_DIM;
    const float* kb = k + (size_t)bh * SEQ * HEAD_DIM;
    const float* vb = v + (size_t)bh * SEQ * HEAD_DIM;
    const size_t moff = (size_t)bh * SEQ * SEQ;

    for (int idx = t; idx < 64 * 32; idx += 512) {
        int r  = idx >> 5;
        int c4 = (idx & 31) * 4;
        float4 x = *(const float4*)&qb[(size_t)(q0 + r) * HEAD_DIM + c4];
        float* qh = smf + OQH + r * FPADD + c4;
        float* ql = smf + OQL + r * FPADD + c4;
        float h0 = to_tf32(x.x); qh[0] = h0; ql[0] = to_tf32(x.x - h0);
        float h1 = to_tf32(x.y); qh[1] = h1; ql[1] = to_tf32(x.y - h1);
        float h2 = to_tf32(x.z); qh[2] = h2; ql[2] = to_tf32(x.z - h2);
        float h3 = to_tf32(x.w); qh[3] = h3; ql[3] = to_tf32(x.w - h3);
    }
    if (t < 64) { smf[ORM + t] = -1e30f; smf[ORL + t] = 0.f; }

    auto issueKV = [&](int jt, int s) {
        const int j0 = jt * 64;
#pragma unroll
        for (int i = 0; i < 4; ++i) {
            int idx = i * 512 + t;
            int r  = idx >> 5;
            int c4 = (idx & 31) * 4;
            const float* kg = &kb[(size_t)(j0 + r) * HEAD_DIM + c4];
            const float* vg = &vb[(size_t)(j0 + r) * HEAD_DIM + c4];
            cpa16(smb + (uint32_t)(OKS + s * 8704 + r * FPADD + c4) * 4, kg);
            cpa16(smb + (uint32_t)(OVS + s * 8448 + r * FPADV + c4) * 4, vg);
        }
        CPA_COMMIT();
    };

    issueKV(0, 0);

    const float SC2  = 0.08838834764831845f * 1.4426950408889634f;
    const float CPM  = 0.05f * 1.4426950408889634f;
    const float CPO  = 0.1f  * 1.4426950408889634f;

    const int row0  = wm + gid;
    const int row1  = row0 + 8;
    const int grow0 = q0 + row0;
    const int grow1 = q0 + row1;

    float acc_o[4][4];
#pragma unroll
    for (int ni = 0; ni < 4; ++ni)
#pragma unroll
        for (int j = 0; j < 4; ++j) acc_o[ni][j] = 0.f;

    for (int jt = 0; jt <= qt; ++jt) {
        cpa_wait<0>();     // stage jt fully arrived
        __syncthreads();   // #1: all warps done with iteration jt-1 (buffers free)

        if (jt < qt) issueKV(jt + 1, (jt + 1) & 1);   // safe: after barrier

        const float* Kb = smf + OKS + (jt & 1) * 8704;
        const float* Vb = smf + OVS + (jt & 1) * 8448;
        const int j0c = jt * 64;

        const size_t mr0 = moff + (size_t)grow0 * SEQ + j0c;
        const size_t mr1 = moff + (size_t)grow1 * SEQ + j0c;
        float2 pa0[2], pb0[2], pc0[2], pa1[2], pb1[2], pc1[2];
#pragma unroll
        for (int ni = 0; ni < 2; ++ni) {
            const int cl = wn + ni * 8 + 2 * tig;
            pa0[ni] = *(const float2*)&pm[mr0 + cl];
            pb0[ni] = *(const float2*)&pol[mr0 + cl];
            pc0[ni] = *(const float2*)&mw[mr0 + cl];
            pa1[ni] = *(const float2*)&pm[mr1 + cl];
            pb1[ni] = *(const float2*)&pol[mr1 + cl];
            pc1[ni] = *(const float2*)&mw[mr1 + cl];
        }

        float accs[2][4];
#pragma unroll
        for (int ni = 0; ni < 2; ++ni)
#pragma unroll
            for (int j = 0; j < 4; ++j) accs[ni][j] = 0.f;

#pragma unroll
        for (int ks = 0; ks < 16; ++ks) {
            const int kk = ks * 8 + 2 * tig;     // slice-permuted adjacent pair
            uint32_t ah[4], al[4], b[2][2];
            const float* Qh = smf + OQH;
            const float* Ql = smf + OQL;
            uint2 h0 = *(const uint2*)&Qh[row0 * FPADD + kk];
            uint2 h1 = *(const uint2*)&Qh[row1 * FPADD + kk];
            uint2 l0 = *(const uint2*)&Ql[row0 * FPADD + kk];
            uint2 l1 = *(const uint2*)&Ql[row1 * FPADD + kk];
            ah[0] = h0.x; ah[2] = h0.y; ah[1] = h1.x; ah[3] = h1.y;
            al[0] = l0.x; al[2] = l0.y; al[1] = l1.x; al[3] = l1.y;
#pragma unroll
            for (int ni = 0; ni < 2; ++ni) {
                const int c = wn + ni * 8 + gid;
                uint2 bv = *(const uint2*)&Kb[c * FPADD + kk];
                b[ni][0] = bv.x; b[ni][1] = bv.y;
            }
#pragma unroll
            for (int ni = 0; ni < 2; ++ni) {
                mma16n8k8(accs[ni], ah, b[ni]);
                mma16n8k8(accs[ni], al, b[ni]);
            }
        }

        const bool diag = (jt == qt);
        float ml0 = -1e30f, ml1 = -1e30f;
#pragma unroll
        for (int ni = 0; ni < 2; ++ni) {
            const int cl = wn + ni * 8 + 2 * tig;
            float s0 = fmaf(accs[ni][0], SC2, fmaf(pa0[ni].x, CPM, fmaf(pb0[ni].x, CPO, log2p_small(fmaf(pc0[ni].x, 0.1f, 1e-8f)))));
            float s1 = fmaf(accs[ni][1], SC2, fmaf(pa0[ni].y, CPM, fmaf(pb0[ni].y, CPO, log2p_small(fmaf(pc0[ni].y, 0.1f, 1e-8f)))));
            float s2 = fmaf(accs[ni][2], SC2, fmaf(pa1[ni].x, CPM, fmaf(pb1[ni].x, CPO, log2p_small(fmaf(pc1[ni].x, 0.1f, 1e-8f)))));
            float s3 = fmaf(accs[ni][3], SC2, fmaf(pa1[ni].y, CPM, fmaf(pb1[ni].y, CPO, log2p_small(fmaf(pc1[ni].y, 0.1f, 1e-8f)))));
            if (diag) {
                if (cl     > row0) s0 = -1e30f;
                if (cl + 1 > row0) s1 = -1e30f;
                if (cl     > row1) s2 = -1e30f;
                if (cl + 1 > row1) s3 = -1e30f;
            }
            accs[ni][0] = s0; accs[ni][1] = s1; accs[ni][2] = s2; accs[ni][3] = s3;
            ml0 = fmaxf(ml0, fmaxf(s0, s1));
            ml1 = fmaxf(ml1, fmaxf(s2, s3));
        }
#pragma unroll
        for (int o = 1; o < 4; o <<= 1) {
            ml0 = fmaxf(ml0, __shfl_xor_sync(0xffffffffu, ml0, o));
            ml1 = fmaxf(ml1, __shfl_xor_sync(0xffffffffu, ml1, o));
        }
        if (tig == 0) {
            smf[ORDM + wni * 64 + row0] = ml0;
            smf[ORDM + wni * 64 + row1] = ml1;
        }
        float mold0 = smf[ORM + row0];
        float mold1 = smf[ORM + row1];
        __syncthreads();   // #2: redm ready

        float mn0 = fmaxf(fmaxf(mold0, fmaxf(smf[ORDM + row0], smf[ORDM + 64 + row0])),
                          fmaxf(smf[ORDM + 128 + row0], smf[ORDM + 192 + row0]));
        float mn1 = fmaxf(fmaxf(mold1, fmaxf(smf[ORDM + row1], smf[ORDM + 64 + row1])),
                          fmaxf(smf[ORDM + 128 + row1], smf[ORDM + 192 + row1]));
        float al0 = exp2c(mold0 - mn0);
        float al1 = exp2c(mold1 - mn1);

        float sum0 = 0.f, sum1 = 0.f;
#pragma unroll
        for (int ni = 0; ni < 2; ++ni) {
            const int cl = wn + ni * 8 + 2 * tig;
            float p0 = exp2c(accs[ni][0] - mn0);
            float p1 = exp2c(accs[ni][1] - mn0);
            float p2 = exp2c(accs[ni][2] - mn1);
            float p3 = exp2c(accs[ni][3] - mn1);
            sum0 += p0 + p1;
            sum1 += p2 + p3;
            smf[OPS + row0 * FPADP + cl]     = to_tf32(p0);
            smf[OPS + row0 * FPADP + cl + 1] = to_tf32(p1);
            smf[OPS + row1 * FPADP + cl]     = to_tf32(p2);
            smf[OPS + row1 * FPADP + cl + 1] = to_tf32(p3);
        }
#pragma unroll
        for (int o = 1; o < 4; o <<= 1) {
            sum0 += __shfl_xor_sync(0xffffffffu, sum0, o);
            sum1 += __shfl_xor_sync(0xffffffffu, sum1, o);
        }
        if (tig == 0) {
            smf[ORDS + wni * 64 + row0] = sum0;
            smf[ORDS + wni * 64 + row1] = sum1;
        }
#pragma unroll
        for (int ni = 0; ni < 4; ++ni) {
            acc_o[ni][0] *= al0; acc_o[ni][1] *= al0;
            acc_o[ni][2] *= al1; acc_o[ni][3] *= al1;
        }
        __syncthreads();   // #3: Ps + reds ready

        if (t < 64) {
            float mo = smf[ORM + t];
            float mn = fmaxf(fmaxf(mo, fmaxf(smf[ORDM + t], smf[ORDM + 64 + t])),
                             fmaxf(smf[ORDM + 128 + t], smf[ORDM + 192 + t]));
            float a  = exp2c(mo - mn);
            smf[ORL + t] = smf[ORL + t] * a
                         + smf[ORDS + t] + smf[ORDS + 64 + t]
                         + smf[ORDS + 128 + t] + smf[ORDS + 192 + t];
            smf[ORM + t] = mn;
        }

        const float* Pu = smf + OPS;
        const float* Vu = Vb;
#pragma unroll
        for (int ks = 0; ks < 8; ++ks) {
            const int kk = ks * 8 + 2 * tig;     // slice-permuted pair
            uint32_t a[4], b[4][2];
            uint2 p0 = *(const uint2*)&Pu[row0 * FPADP + kk];
            uint2 p1 = *(const uint2*)&Pu[row1 * FPADP + kk];
            a[0] = p0.x; a[2] = p0.y; a[1] = p1.x; a[3] = p1.y;
#pragma unroll
            for (int ni = 0; ni < 4; ++ni) {
                const int c = wd + ni * 8 + gid;
                b[ni][0] = *(const uint32_t*)&Vu[kk * FPADV + c];
                b[ni][1] = *(const uint32_t*)&Vu[(kk + 1) * FPADV + c];
            }
#pragma unroll
            for (int ni = 0; ni < 4; ++ni)
                mma16n8k8(acc_o[ni], a, b[ni]);
        }
    }

    __syncthreads();
    const float l0 = 1.f / smf[ORL + row0];
    const float l1 = 1.f / smf[ORL + row1];
    const int bb = bh >> 4;
    const int h  = bh & 15;
    float* o0 = attn + ((size_t)(bb * SEQ + grow0)) * HIDDEN + h * HEAD_DIM;
    float* o1 = attn + ((size_t)(bb * SEQ + grow1)) * HIDDEN + h * HEAD_DIM;
#pragma unroll
    for (int ni = 0; ni < 4; ++ni) {
        const int d = wd + ni * 8 + 2 * tig;
        float2 w0 = {to_tf32(acc_o[ni][0] * l0), to_tf32(acc_o[ni][1] * l0)};
        float2 w1 = {to_tf32(acc_o[ni][2] * l1), to_tf32(acc_o[ni][3] * l1)};
        *(float2*)(o0 + d) = w0;
        *(float2*)(o1 + d) = w1;
    }
}

// ============================================================================
// host launcher
// ============================================================================
extern "C" void kernel_launch(void* const* d_in, const int* in_sizes, int n_in,
                              void* d_out, int out_size)
{
    const float* x   = (const float*)d_in[0];
    const float* pm  = (const float*)d_in[1];
    const float* pol = (const float*)d_in[2];
    const float* mw  = (const float*)d_in[3];
    const float* Wq  = (const float*)d_in[4];
    const float* Wk  = (const float*)d_in[5];
    const float* Wv  = (const float*)d_in[6];
    const float* Wo  = (const float*)d_in[7];
    const float* bo  = (const float*)d_in[8];
    float* out = (float*)d_out;

    float *gq, *gk, *gv, *ga, *gw, *gx;
    cudaGetSymbolAddress((void**)&gq, g_q);
    cudaGetSymbolAddress((void**)&gk, g_k);
    cudaGetSymbolAddress((void**)&gv, g_v);
    cudaGetSymbolAddress((void**)&ga, g_attn);
    cudaGetSymbolAddress((void**)&gw, g_wt);
    cudaGetSymbolAddress((void**)&gx, g_xc);

    cudaFuncSetAttribute(flash_kernel,
                         cudaFuncAttributeMaxDynamicSharedMemorySize, FLASH_SMEM);
    cudaFuncSetAttribute(gemm_mma_kernel,
                         cudaFuncAttributeMaxDynamicSharedMemorySize, GEMM_SMEM);

    float* wtq = gw;
    float* wtk = gw + (size_t)HIDDEN * HIDDEN;
    float* wtv = gw + 2 * (size_t)HIDDEN * HIDDEN;
    float* wto = gw + 3 * (size_t)HIDDEN * HIDDEN;

    // K0: tf32-round x; transpose+round weights to [N,K]
    const int n4 = HIDDEN * HIDDEN / 4;
    cvt_tf32_kernel<<<(n4 + 255) / 256, 256>>>(x, gx, n4);
    transpose2048<<<dim3(64, 64, 4), 256>>>(Wq, Wk, Wv, Wo, gw);

    // K1: QKV projections
    gemm_mma_kernel<<<dim3(HIDDEN / BN, MROWS / BM, 3), 128, GEMM_SMEM>>>(
        gx, wtq, wtk, wtv, gq, gk, gv, nullptr, 1);

    // K2: RoPE + tf32 rounding of k, v
    int rope_n = BATCH * HEADS * SEQ * 64;
    rope_kernel<<<(rope_n + 255) / 256, 256>>>(gq, gk, gv);

    // K3: tensor-core flash attention
    dim3 gfl(SEQ / 64, BATCH * HEADS);
    flash_kernel<<<gfl, 512, FLASH_SMEM>>>(gq, gk, gv, pm, pol, mw, ga);

    // K4: output projection + bias
    gemm_mma_kernel<<<dim3(HIDDEN / BN, MROWS / BM, 1), 128, GEMM_SMEM>>>(
        ga, wto, wto, wto, out, out, out, bo, 0);
}